// round 7
// baseline (speedup 1.0000x reference)
#include <cuda_runtime.h>
#include <cuda_bf16.h>
#include <cstdint>
#include <math.h>

#define S 2048
#define DMODEL 512
#define NH 8
#define DKH 64
#define WIN 64
#define NEGV -1000000000.0f
#define SD (S*DMODEL)
#define DD (DMODEL*DMODEL)

#define QS_STR 68
#define KS_STR 132
#define VS_STR 68
#define PS_STR 68

#define LDA 40

typedef unsigned int u32;

// ---------------- device scratch (allocation-free rule) ----------------
__device__ __nv_bfloat16 g_xh[3*SD];
__device__ __nv_bfloat16 g_xl[3*SD];
__device__ __nv_bfloat16 g_Wh[4*DD];
__device__ __nv_bfloat16 g_Wl[4*DD];
__device__ float g_QKV[3*SD];     // QKV projections; later reused as split-K partials
__device__ __nv_bfloat16 g_AOh[SD];
__device__ __nv_bfloat16 g_AOl[SD];

// ---------------- fp32 -> bf16 hi/lo split ----------------
__global__ void __launch_bounds__(256) convert_split(
    const float* __restrict__ q, const float* __restrict__ k, const float* __restrict__ v,
    const float* __restrict__ Wq, const float* __restrict__ Wk,
    const float* __restrict__ Wv, const float* __restrict__ Wo)
{
    const int SD4 = SD/4;
    const int DD4 = DD/4;
    int idx = blockIdx.x * 256 + threadIdx.x;
    const float* src;
    __nv_bfloat16* dh;
    __nv_bfloat16* dl;
    if (idx < 3*SD4) {
        int r = idx / SD4;
        size_t e = (size_t)(idx - r*SD4) * 4;
        src = (r == 0 ? q : (r == 1 ? k : v)) + e;
        dh = g_xh + (size_t)r*SD + e;
        dl = g_xl + (size_t)r*SD + e;
    } else {
        int j = idx - 3*SD4;
        int r = j / DD4;
        size_t e = (size_t)(j - r*DD4) * 4;
        src = (r == 0 ? Wq : (r == 1 ? Wk : (r == 2 ? Wv : Wo))) + e;
        dh = g_Wh + (size_t)r*DD + e;
        dl = g_Wl + (size_t)r*DD + e;
    }
    float4 f = *(const float4*)src;
    __nv_bfloat16 h0 = __float2bfloat16(f.x);
    __nv_bfloat16 h1 = __float2bfloat16(f.y);
    __nv_bfloat16 h2 = __float2bfloat16(f.z);
    __nv_bfloat16 h3 = __float2bfloat16(f.w);
    __nv_bfloat16 l0 = __float2bfloat16(f.x - __bfloat162float(h0));
    __nv_bfloat16 l1 = __float2bfloat16(f.y - __bfloat162float(h1));
    __nv_bfloat16 l2 = __float2bfloat16(f.z - __bfloat162float(h2));
    __nv_bfloat16 l3 = __float2bfloat16(f.w - __bfloat162float(h3));
    *(__nv_bfloat162*)(dh)     = __halves2bfloat162(h0, h1);
    *(__nv_bfloat162*)(dh + 2) = __halves2bfloat162(h2, h3);
    *(__nv_bfloat162*)(dl)     = __halves2bfloat162(l0, l1);
    *(__nv_bfloat162*)(dl + 2) = __halves2bfloat162(l2, l3);
}

// ---------------- tensor-core GEMM helpers ----------------
__device__ __forceinline__ void ldsm4(u32* r, u32 a) {
    asm volatile("ldmatrix.sync.aligned.m8n8.x4.shared.b16 {%0,%1,%2,%3}, [%4];"
        : "=r"(r[0]), "=r"(r[1]), "=r"(r[2]), "=r"(r[3]) : "r"(a));
}
__device__ __forceinline__ void mma_bf16(float* c, const u32* a, const u32* b) {
    asm volatile("mma.sync.aligned.m16n8k16.row.col.f32.bf16.bf16.f32 "
        "{%0,%1,%2,%3},{%4,%5,%6,%7},{%8,%9},{%0,%1,%2,%3};"
        : "+f"(c[0]), "+f"(c[1]), "+f"(c[2]), "+f"(c[3])
        : "r"(a[0]), "r"(a[1]), "r"(a[2]), "r"(a[3]), "r"(b[0]), "r"(b[1]));
}
__device__ __forceinline__ void cp16(u32 dst, const void* src) {
    asm volatile("cp.async.cg.shared.global [%0], [%1], 16;" :: "r"(dst), "l"(src));
}
__device__ __forceinline__ void cp_commit() {
    asm volatile("cp.async.commit_group;");
}

// Per-stage byte sizes in dynamic smem; 2-stage double buffer (round-5 best)
#define STG_A (128*LDA*2)
#define STG_W (64*LDA*2)
#define SMEM_GEMM (2*(2*STG_A + 2*STG_W))

// C[M,N] = A[M,K(range)] @ W[N,K(range)]^T (+bias). Split-bf16 3-term.
// Tile 128x64, BK=32, double-buffered cp.async pipeline.
// splitk==0: blockIdx.z selects (A,W,C) matrix triple (QKV); K = full 512.
// splitk==1: blockIdx.z selects K-half; C = partials at C + z*SD; no bias.
__global__ void __launch_bounds__(256, 2) gemm128x64(
    const __nv_bfloat16* __restrict__ Ah_, const __nv_bfloat16* __restrict__ Al_,
    const __nv_bfloat16* __restrict__ Wh_, const __nv_bfloat16* __restrict__ Wl_,
    float* __restrict__ C, const float* __restrict__ bias, int splitk)
{
    extern __shared__ __align__(16) __nv_bfloat16 dsm[];

    size_t za, zw, zc;
    int kbeg, nst;
    if (splitk) {
        za = 0;
        zw = 0;
        zc = (size_t)blockIdx.z * SD;
        kbeg = blockIdx.z * 256;
        nst = 8;
    } else {
        za = (size_t)blockIdx.z * SD;
        zw = (size_t)blockIdx.z * DD;
        zc = za;
        kbeg = 0;
        nst = 16;
    }

    const int tid = threadIdx.x;
    const int m_base = blockIdx.y * 128;
    const int n_base = blockIdx.x * 64;

    const int a_row = tid >> 2;
    const int a_col = (tid & 3) * 8;

    const int lane = tid & 31;
    const int wid = tid >> 5;
    const int warp_m = wid >> 1;
    const int warp_n = wid & 1;
    const int lrow = (lane & 7) + ((lane >> 3) & 1) * 8;
    const int lcol = (lane >> 4) * 8;

    const u32 base = (u32)__cvta_generic_to_shared(dsm);
    const u32 bAh = base;
    const u32 bAl = base + 2*STG_A;
    const u32 bWh = base + 4*STG_A;
    const u32 bWl = base + 4*STG_A + 2*STG_W;

    const __nv_bfloat16* gA  = Ah_ + za + (size_t)(m_base + a_row) * DMODEL + kbeg + a_col;
    const __nv_bfloat16* gL  = Al_ + za + (size_t)(m_base + a_row) * DMODEL + kbeg + a_col;
    const __nv_bfloat16* gW  = Wh_ + zw + (size_t)(n_base + a_row) * DMODEL + kbeg + a_col;
    const __nv_bfloat16* gWl = Wl_ + zw + (size_t)(n_base + a_row) * DMODEL + kbeg + a_col;
    float* Cz = C + zc;

    const u32 aoff = (u32)((a_row * LDA + a_col) * 2);

    float acc[2][4][4];
    #pragma unroll
    for (int mi = 0; mi < 2; mi++) {
        #pragma unroll
        for (int ni = 0; ni < 4; ni++) {
            #pragma unroll
            for (int t = 0; t < 4; t++) {
                acc[mi][ni][t] = 0.0f;
            }
        }
    }

    // prologue: stage 0
    {
        cp16(bAh + aoff, gA);
        cp16(bAh + aoff + (u32)(64*LDA*2), gA + 64 * DMODEL);
        cp16(bAl + aoff, gL);
        cp16(bAl + aoff + (u32)(64*LDA*2), gL + 64 * DMODEL);
        cp16(bWh + aoff, gW);
        cp16(bWl + aoff, gWl);
        cp_commit();
    }

    for (int s = 0; s < nst; s++) {
        const u32 bufA = (u32)(s & 1) * STG_A;
        const u32 bufW = (u32)(s & 1) * STG_W;

        if (s < nst - 1) {
            int k0 = (s + 1) * 32;
            u32 nbA = (u32)((s + 1) & 1) * STG_A;
            u32 nbW = (u32)((s + 1) & 1) * STG_W;
            cp16(bAh + nbA + aoff, gA + k0);
            cp16(bAh + nbA + aoff + (u32)(64*LDA*2), gA + k0 + 64 * DMODEL);
            cp16(bAl + nbA + aoff, gL + k0);
            cp16(bAl + nbA + aoff + (u32)(64*LDA*2), gL + k0 + 64 * DMODEL);
            cp16(bWh + nbW + aoff, gW + k0);
            cp16(bWl + nbW + aoff, gWl + k0);
            cp_commit();
            asm volatile("cp.async.wait_group 1;");
        } else {
            asm volatile("cp.async.wait_group 0;");
        }
        __syncthreads();

        #pragma unroll
        for (int kb = 0; kb < 32; kb += 16) {
            u32 ah[2][4];
            u32 al[2][4];
            u32 bh[4][2];
            u32 bl[4][2];
            #pragma unroll
            for (int mi = 0; mi < 2; mi++) {
                u32 off = bufA + (u32)(((warp_m * 32 + mi * 16 + lrow) * LDA + kb + lcol) * 2);
                ldsm4(ah[mi], bAh + off);
                ldsm4(al[mi], bAl + off);
            }
            #pragma unroll
            for (int g2 = 0; g2 < 2; g2++) {
                u32 off = bufW + (u32)(((warp_n * 32 + g2 * 16 + lrow) * LDA + kb + lcol) * 2);
                u32 r0[4];
                ldsm4(r0, bWh + off);
                bh[g2*2][0]   = r0[0];
                bh[g2*2+1][0] = r0[1];
                bh[g2*2][1]   = r0[2];
                bh[g2*2+1][1] = r0[3];
                u32 r1[4];
                ldsm4(r1, bWl + off);
                bl[g2*2][0]   = r1[0];
                bl[g2*2+1][0] = r1[1];
                bl[g2*2][1]   = r1[2];
                bl[g2*2+1][1] = r1[3];
            }
            #pragma unroll
            for (int mi = 0; mi < 2; mi++) {
                #pragma unroll
                for (int ni = 0; ni < 4; ni++) {
                    mma_bf16(acc[mi][ni], ah[mi], bh[ni]);
                    mma_bf16(acc[mi][ni], ah[mi], bl[ni]);
                    mma_bf16(acc[mi][ni], al[mi], bh[ni]);
                }
            }
        }
        __syncthreads();
    }

    const int qr = lane >> 2;
    const int qc = (lane & 3) * 2;
    #pragma unroll
    for (int mi = 0; mi < 2; mi++) {
        int m0 = m_base + warp_m * 32 + mi * 16 + qr;
        #pragma unroll
        for (int ni = 0; ni < 4; ni++) {
            int n = n_base + warp_n * 32 + ni * 8 + qc;
            float b0 = 0.0f;
            float b1 = 0.0f;
            if (bias) {
                b0 = bias[n];
                b1 = bias[n + 1];
            }
            float2 v0 = make_float2(acc[mi][ni][0] + b0, acc[mi][ni][1] + b1);
            float2 v1 = make_float2(acc[mi][ni][2] + b0, acc[mi][ni][3] + b1);
            *(float2*)(Cz + (size_t)m0 * DMODEL + n) = v0;
            *(float2*)(Cz + (size_t)(m0 + 8) * DMODEL + n) = v1;
        }
    }
}

// ---------------- split-K reduce: out = P0 + P1 + bias ----------------
__global__ void __launch_bounds__(256) reduce_splitk(
    const float* __restrict__ P, const float* __restrict__ bias,
    float* __restrict__ out)
{
    int idx = blockIdx.x * 256 + threadIdx.x;   // float4 index, total SD/4
    float4 a = ((const float4*)P)[idx];
    float4 b = ((const float4*)P)[idx + SD/4];
    float4 bb = ((const float4*)bias)[idx & 127];   // 512/4 = 128 float4 per row
    float4 o;
    o.x = a.x + b.x + bb.x;
    o.y = a.y + b.y + bb.y;
    o.z = a.z + b.z + bb.z;
    o.w = a.w + b.w + bb.w;
    ((float4*)out)[idx] = o;
}

// ---------------- windowed attention ----------------
__global__ void __launch_bounds__(256) local_attn(
    const float* __restrict__ Q, const float* __restrict__ K,
    const float* __restrict__ V, float* __restrict__ attn_w)
{
    extern __shared__ __align__(16) float sm[];
    float* Qs = sm;
    float* Ks = sm + 64*QS_STR;
    float* Vs = sm + 64*QS_STR + 64*KS_STR;
    float* bias_s = Vs + 128*VS_STR;
    float* Ps = sm;   // aliases Qs+Ks after scores move to registers

    const int h  = blockIdx.y;
    const int i0 = blockIdx.x * 64;
    const int tid = threadIdx.x;

    if (tid <= WIN) {
        bias_s[tid] = 0.1f * expf(-0.1f * (float)(WIN - tid));
    }

    for (int idx = tid; idx < 64 * 64; idx += 256) {
        int qi = idx >> 6;
        int d  = idx & 63;
        Qs[d * QS_STR + qi] = Q[(size_t)(i0 + qi) * DMODEL + h * DKH + d];
    }
    for (int idx = tid; idx < 128 * 64; idx += 256) {
        int kk = idx >> 6;
        int d  = idx & 63;
        int j = i0 - 64 + kk;
        int jc = (j < 0) ? 0 : j;
        Ks[d * KS_STR + kk] = K[(size_t)jc * DMODEL + h * DKH + d];
        Vs[kk * VS_STR + d] = V[(size_t)jc * DMODEL + h * DKH + d];
    }
    __syncthreads();

    const int tx = tid & 15;
    const int ty = tid >> 4;
    const int qi0 = ty * 4;
    const int kk0 = tx * 8;

    float sc[4][8];
    #pragma unroll
    for (int i = 0; i < 4; i++) {
        #pragma unroll
        for (int j = 0; j < 8; j++) {
            sc[i][j] = 0.0f;
        }
    }
    #pragma unroll 8
    for (int d = 0; d < 64; d++) {
        float4 a  = *(const float4*)&Qs[d * QS_STR + qi0];
        float4 b0 = *(const float4*)&Ks[d * KS_STR + kk0];
        float4 b1 = *(const float4*)&Ks[d * KS_STR + kk0 + 4];
        float av[4] = {a.x, a.y, a.z, a.w};
        float bv[8] = {b0.x, b0.y, b0.z, b0.w, b1.x, b1.y, b1.z, b1.w};
        #pragma unroll
        for (int i = 0; i < 4; i++) {
            #pragma unroll
            for (int j = 0; j < 8; j++) {
                sc[i][j] = fmaf(av[i], bv[j], sc[i][j]);
            }
        }
    }
    __syncthreads();   // scores in regs; safe to overwrite Qs/Ks with Ps

    #pragma unroll
    for (int i = 0; i < 4; i++) {
        #pragma unroll
        for (int j = 0; j < 8; j++) {
            int qi = qi0 + i;
            int kk = kk0 + j;
            int r  = kk - qi;
            int jg = i0 - 64 + kk;
            float val = NEGV;
            if (r >= 0 && r <= WIN && jg >= 0) {
                val = sc[i][j] * 0.125f + bias_s[r];
            }
            Ps[kk * PS_STR + qi] = val;
        }
    }
    __syncthreads();

    {
        const int warp = tid >> 5;
        const int lane = tid & 31;
        for (int rr = 0; rr < 8; rr++) {
            int qi = warp * 8 + rr;
            float v[4];
            float mx = -3.4e38f;
            #pragma unroll
            for (int t = 0; t < 4; t++) {
                v[t] = Ps[(lane + t * 32) * PS_STR + qi];
                mx = fmaxf(mx, v[t]);
            }
            #pragma unroll
            for (int o = 16; o > 0; o >>= 1) {
                mx = fmaxf(mx, __shfl_xor_sync(0xffffffffu, mx, o));
            }
            float sum = 0.0f;
            #pragma unroll
            for (int t = 0; t < 4; t++) {
                v[t] = expf(v[t] - mx);
                sum += v[t];
            }
            #pragma unroll
            for (int o = 16; o > 0; o >>= 1) {
                sum += __shfl_xor_sync(0xffffffffu, sum, o);
            }
            float inv = 1.0f / sum;
            #pragma unroll
            for (int t = 0; t < 4; t++) {
                Ps[(lane + t * 32) * PS_STR + qi] = v[t] * inv;
            }
        }
    }
    __syncthreads();

    for (int idx = tid; idx < 64 * 128; idx += 256) {
        int qi = idx >> 7;
        int slot = idx & 127;
        int i = i0 + qi;
        float val = 0.0f;
        if (i < WIN) {
            if (slot <= qi) {
                val = Ps[(slot + 64) * PS_STR + qi];
            }
        } else if (i >= S - WIN) {
            if (slot <= WIN) {
                val = Ps[(qi + slot) * PS_STR + qi];
            }
        }
        attn_w[((size_t)h * S + i) * 128 + slot] = val;
    }

    const int dk0 = tx * 4;
    float acc[4][4];
    #pragma unroll
    for (int i = 0; i < 4; i++) {
        #pragma unroll
        for (int j = 0; j < 4; j++) {
            acc[i][j] = 0.0f;
        }
    }
    #pragma unroll 4
    for (int kk = 0; kk < 128; kk++) {
        float4 p  = *(const float4*)&Ps[kk * PS_STR + qi0];
        float4 vv = *(const float4*)&Vs[kk * VS_STR + dk0];
        float pv[4] = {p.x, p.y, p.z, p.w};
        float vb[4] = {vv.x, vv.y, vv.z, vv.w};
        #pragma unroll
        for (int i = 0; i < 4; i++) {
            #pragma unroll
            for (int j = 0; j < 4; j++) {
                acc[i][j] = fmaf(pv[i], vb[j], acc[i][j]);
            }
        }
    }
    #pragma unroll
    for (int i = 0; i < 4; i++) {
        size_t base = (size_t)(i0 + qi0 + i) * DMODEL + h * DKH + dk0;
        __nv_bfloat16 hh[4];
        __nv_bfloat16 ll[4];
        #pragma unroll
        for (int j = 0; j < 4; j++) {
            float vv = acc[i][j];
            hh[j] = __float2bfloat16(vv);
            ll[j] = __float2bfloat16(vv - __bfloat162float(hh[j]));
        }
        *(__nv_bfloat162*)(g_AOh + base)     = __halves2bfloat162(hh[0], hh[1]);
        *(__nv_bfloat162*)(g_AOh + base + 2) = __halves2bfloat162(hh[2], hh[3]);
        *(__nv_bfloat162*)(g_AOl + base)     = __halves2bfloat162(ll[0], ll[1]);
        *(__nv_bfloat162*)(g_AOl + base + 2) = __halves2bfloat162(ll[2], ll[3]);
    }
}

// ---------------- launch ----------------
extern "C" void kernel_launch(void* const* d_in, const int* in_sizes, int n_in,
                              void* d_out, int out_size) {
    const float* q  = (const float*)d_in[0];
    const float* k  = (const float*)d_in[1];
    const float* v  = (const float*)d_in[2];
    const float* Wq = (const float*)d_in[3];
    const float* Wk = (const float*)d_in[4];
    const float* Wv = (const float*)d_in[5];
    const float* Wo = (const float*)d_in[6];
    const float* bo = (const float*)d_in[7];

    float* out    = (float*)d_out;
    float* attn_w = out + (size_t)SD;

    __nv_bfloat16* pxh;
    __nv_bfloat16* pxl;
    __nv_bfloat16* pwh;
    __nv_bfloat16* pwl;
    __nv_bfloat16* paoh;
    __nv_bfloat16* paol;
    float* pqkv;
    cudaGetSymbolAddress((void**)&pxh,  g_xh);
    cudaGetSymbolAddress((void**)&pxl,  g_xl);
    cudaGetSymbolAddress((void**)&pwh,  g_Wh);
    cudaGetSymbolAddress((void**)&pwl,  g_Wl);
    cudaGetSymbolAddress((void**)&pqkv, g_QKV);
    cudaGetSymbolAddress((void**)&paoh, g_AOh);
    cudaGetSymbolAddress((void**)&paol, g_AOl);

    const int SMEM_ATTN = (64*QS_STR + 64*KS_STR + 128*VS_STR + 72) * (int)sizeof(float);
    cudaFuncSetAttribute(local_attn, cudaFuncAttributeMaxDynamicSharedMemorySize, SMEM_ATTN);
    cudaFuncSetAttribute(gemm128x64, cudaFuncAttributeMaxDynamicSharedMemorySize, SMEM_GEMM);
    cudaFuncSetAttribute(gemm128x64, cudaFuncAttributePreferredSharedMemoryCarveout, 100);

    convert_split<<<4096, 256>>>(q, k, v, Wq, Wk, Wv, Wo);

    // QKV projections
    gemm128x64<<<dim3(DMODEL/64, S/128, 3), 256, SMEM_GEMM>>>(
        pxh, pxl, pwh, pwl, pqkv, nullptr, 0);

    local_attn<<<dim3(S/64, NH), 256, SMEM_ATTN>>>(pqkv, pqkv + SD, pqkv + 2*SD, attn_w);

    // O-projection, split-K=2 into partials (reusing g_QKV scratch), then reduce
    gemm128x64<<<dim3(DMODEL/64, S/128, 2), 256, SMEM_GEMM>>>(
        paoh, paol, pwh + 3*DD, pwl + 3*DD, pqkv, nullptr, 1);

    reduce_splitk<<<SD/4/256, 256>>>(pqkv, bo, out);
}

// round 8
// speedup vs baseline: 1.2126x; 1.2126x over previous
#include <cuda_runtime.h>
#include <cuda_fp16.h>
#include <cstdint>
#include <math.h>

#define S 2048
#define DMODEL 512
#define NH 8
#define DKH 64
#define WIN 64
#define NEGV -1000000000.0f
#define SD (S*DMODEL)
#define DD (DMODEL*DMODEL)

#define QS_STR 68
#define KS_STR 132
#define VS_STR 68
#define PS_STR 68

#define LDA 40

typedef unsigned int u32;

// ---------------- device scratch (allocation-free rule) ----------------
__device__ __half g_xh[3*SD];     // activations hi
__device__ __half g_xl[3*SD];     // activations lo
__device__ __half g_Wh[4*DD];     // weights (fp16, single precision level)
__device__ float  g_QKV[3*SD];
__device__ __half g_AOh[SD];
__device__ __half g_AOl[SD];

// ---------------- fp32 -> fp16 split (A: hi/lo, W: hi only) ----------------
__global__ void __launch_bounds__(256) convert_split(
    const float* __restrict__ q, const float* __restrict__ k, const float* __restrict__ v,
    const float* __restrict__ Wq, const float* __restrict__ Wk,
    const float* __restrict__ Wv, const float* __restrict__ Wo)
{
    const int SD4 = SD/4;
    const int DD4 = DD/4;
    int idx = blockIdx.x * 256 + threadIdx.x;
    if (idx < 3*SD4) {
        int r = idx / SD4;
        size_t e = (size_t)(idx - r*SD4) * 4;
        const float* src = (r == 0 ? q : (r == 1 ? k : v)) + e;
        __half* dh = g_xh + (size_t)r*SD + e;
        __half* dl = g_xl + (size_t)r*SD + e;
        float4 f = *(const float4*)src;
        __half h0 = __float2half(f.x);
        __half h1 = __float2half(f.y);
        __half h2 = __float2half(f.z);
        __half h3 = __float2half(f.w);
        __half l0 = __float2half(f.x - __half2float(h0));
        __half l1 = __float2half(f.y - __half2float(h1));
        __half l2 = __float2half(f.z - __half2float(h2));
        __half l3 = __float2half(f.w - __half2float(h3));
        *(__half2*)(dh)     = __halves2half2(h0, h1);
        *(__half2*)(dh + 2) = __halves2half2(h2, h3);
        *(__half2*)(dl)     = __halves2half2(l0, l1);
        *(__half2*)(dl + 2) = __halves2half2(l2, l3);
    } else {
        int j = idx - 3*SD4;
        int r = j / DD4;
        size_t e = (size_t)(j - r*DD4) * 4;
        const float* src = (r == 0 ? Wq : (r == 1 ? Wk : (r == 2 ? Wv : Wo))) + e;
        __half* dh = g_Wh + (size_t)r*DD + e;
        float4 f = *(const float4*)src;
        *(__half2*)(dh)     = __halves2half2(__float2half(f.x), __float2half(f.y));
        *(__half2*)(dh + 2) = __halves2half2(__float2half(f.z), __float2half(f.w));
    }
}

// ---------------- tensor-core GEMM helpers ----------------
__device__ __forceinline__ void ldsm4(u32* r, u32 a) {
    asm volatile("ldmatrix.sync.aligned.m8n8.x4.shared.b16 {%0,%1,%2,%3}, [%4];"
        : "=r"(r[0]), "=r"(r[1]), "=r"(r[2]), "=r"(r[3]) : "r"(a));
}
__device__ __forceinline__ void mma_fp16(float* c, const u32* a, const u32* b) {
    asm volatile("mma.sync.aligned.m16n8k16.row.col.f32.f16.f16.f32 "
        "{%0,%1,%2,%3},{%4,%5,%6,%7},{%8,%9},{%0,%1,%2,%3};"
        : "+f"(c[0]), "+f"(c[1]), "+f"(c[2]), "+f"(c[3])
        : "r"(a[0]), "r"(a[1]), "r"(a[2]), "r"(a[3]), "r"(b[0]), "r"(b[1]));
}
__device__ __forceinline__ void cp16(u32 dst, const void* src) {
    asm volatile("cp.async.cg.shared.global [%0], [%1], 16;" :: "r"(dst), "l"(src));
}
__device__ __forceinline__ void cp_commit() {
    asm volatile("cp.async.commit_group;");
}

// Per-stage byte sizes; 2-stage double buffer
#define STG_A (128*LDA*2)
#define STG_W (64*LDA*2)
#define SMEM_GEMM (2*(2*STG_A + STG_W))

// C[M,N] = A[M,K] @ W[N,K]^T (+bias). fp16 2-term: Ah*Wh + Al*Wh.
// Tile 128x64, BK=32, double-buffered cp.async pipeline.
__global__ void __launch_bounds__(256, 2) gemm128x64(
    const __half* __restrict__ Ah_, const __half* __restrict__ Al_,
    const __half* __restrict__ Wh_,
    float* __restrict__ C, const float* __restrict__ bias)
{
    extern __shared__ __align__(16) __half dsm[];

    const size_t za = (size_t)blockIdx.z * SD;
    const size_t zw = (size_t)blockIdx.z * DD;
    const int tid = threadIdx.x;
    const int m_base = blockIdx.y * 128;
    const int n_base = blockIdx.x * 64;

    const int a_row = tid >> 2;
    const int a_col = (tid & 3) * 8;

    const int lane = tid & 31;
    const int wid = tid >> 5;
    const int warp_m = wid >> 1;
    const int warp_n = wid & 1;
    const int lrow = (lane & 7) + ((lane >> 3) & 1) * 8;
    const int lcol = (lane >> 4) * 8;

    const u32 base = (u32)__cvta_generic_to_shared(dsm);
    const u32 bAh = base;
    const u32 bAl = base + 2*STG_A;
    const u32 bWh = base + 4*STG_A;

    const __half* gA = Ah_ + za + (size_t)(m_base + a_row) * DMODEL + a_col;
    const __half* gL = Al_ + za + (size_t)(m_base + a_row) * DMODEL + a_col;
    const __half* gW = Wh_ + zw + (size_t)(n_base + a_row) * DMODEL + a_col;
    float* Cz = C + za;

    const u32 aoff = (u32)((a_row * LDA + a_col) * 2);

    float acc[2][4][4];
    #pragma unroll
    for (int mi = 0; mi < 2; mi++) {
        #pragma unroll
        for (int ni = 0; ni < 4; ni++) {
            #pragma unroll
            for (int t = 0; t < 4; t++) {
                acc[mi][ni][t] = 0.0f;
            }
        }
    }

    // prologue: stage 0
    {
        cp16(bAh + aoff, gA);
        cp16(bAh + aoff + (u32)(64*LDA*2), gA + 64 * DMODEL);
        cp16(bAl + aoff, gL);
        cp16(bAl + aoff + (u32)(64*LDA*2), gL + 64 * DMODEL);
        cp16(bWh + aoff, gW);
        cp_commit();
    }

    for (int s = 0; s < 16; s++) {
        const u32 bufA = (u32)(s & 1) * STG_A;
        const u32 bufW = (u32)(s & 1) * STG_W;

        if (s < 15) {
            int k0 = (s + 1) * 32;
            u32 nbA = (u32)((s + 1) & 1) * STG_A;
            u32 nbW = (u32)((s + 1) & 1) * STG_W;
            cp16(bAh + nbA + aoff, gA + k0);
            cp16(bAh + nbA + aoff + (u32)(64*LDA*2), gA + k0 + 64 * DMODEL);
            cp16(bAl + nbA + aoff, gL + k0);
            cp16(bAl + nbA + aoff + (u32)(64*LDA*2), gL + k0 + 64 * DMODEL);
            cp16(bWh + nbW + aoff, gW + k0);
            cp_commit();
            asm volatile("cp.async.wait_group 1;");
        } else {
            asm volatile("cp.async.wait_group 0;");
        }
        __syncthreads();

        #pragma unroll
        for (int kb = 0; kb < 32; kb += 16) {
            u32 ah[2][4];
            u32 al[2][4];
            u32 bh[4][2];
            #pragma unroll
            for (int mi = 0; mi < 2; mi++) {
                u32 off = bufA + (u32)(((warp_m * 32 + mi * 16 + lrow) * LDA + kb + lcol) * 2);
                ldsm4(ah[mi], bAh + off);
                ldsm4(al[mi], bAl + off);
            }
            #pragma unroll
            for (int g2 = 0; g2 < 2; g2++) {
                u32 off = bufW + (u32)(((warp_n * 32 + g2 * 16 + lrow) * LDA + kb + lcol) * 2);
                u32 r0[4];
                ldsm4(r0, bWh + off);
                bh[g2*2][0]   = r0[0];
                bh[g2*2+1][0] = r0[1];
                bh[g2*2][1]   = r0[2];
                bh[g2*2+1][1] = r0[3];
            }
            #pragma unroll
            for (int mi = 0; mi < 2; mi++) {
                #pragma unroll
                for (int ni = 0; ni < 4; ni++) {
                    mma_fp16(acc[mi][ni], ah[mi], bh[ni]);
                    mma_fp16(acc[mi][ni], al[mi], bh[ni]);
                }
            }
        }
        __syncthreads();
    }

    const int qr = lane >> 2;
    const int qc = (lane & 3) * 2;
    #pragma unroll
    for (int mi = 0; mi < 2; mi++) {
        int m0 = m_base + warp_m * 32 + mi * 16 + qr;
        #pragma unroll
        for (int ni = 0; ni < 4; ni++) {
            int n = n_base + warp_n * 32 + ni * 8 + qc;
            float b0 = 0.0f;
            float b1 = 0.0f;
            if (bias) {
                b0 = bias[n];
                b1 = bias[n + 1];
            }
            float2 v0 = make_float2(acc[mi][ni][0] + b0, acc[mi][ni][1] + b1);
            float2 v1 = make_float2(acc[mi][ni][2] + b0, acc[mi][ni][3] + b1);
            *(float2*)(Cz + (size_t)m0 * DMODEL + n) = v0;
            *(float2*)(Cz + (size_t)(m0 + 8) * DMODEL + n) = v1;
        }
    }
}

// ---------------- windowed attention ----------------
__global__ void __launch_bounds__(256) local_attn(
    const float* __restrict__ Q, const float* __restrict__ K,
    const float* __restrict__ V, float* __restrict__ attn_w)
{
    extern __shared__ __align__(16) float sm[];
    float* Qs = sm;
    float* Ks = sm + 64*QS_STR;
    float* Vs = sm + 64*QS_STR + 64*KS_STR;
    float* bias_s = Vs + 128*VS_STR;
    float* Ps = sm;   // aliases Qs+Ks after scores move to registers

    const int h  = blockIdx.y;
    const int i0 = blockIdx.x * 64;
    const int tid = threadIdx.x;

    if (tid <= WIN) {
        bias_s[tid] = 0.1f * expf(-0.1f * (float)(WIN - tid));
    }

    for (int idx = tid; idx < 64 * 64; idx += 256) {
        int qi = idx >> 6;
        int d  = idx & 63;
        Qs[d * QS_STR + qi] = Q[(size_t)(i0 + qi) * DMODEL + h * DKH + d];
    }
    for (int idx = tid; idx < 128 * 64; idx += 256) {
        int kk = idx >> 6;
        int d  = idx & 63;
        int j = i0 - 64 + kk;
        int jc = (j < 0) ? 0 : j;
        Ks[d * KS_STR + kk] = K[(size_t)jc * DMODEL + h * DKH + d];
        Vs[kk * VS_STR + d] = V[(size_t)jc * DMODEL + h * DKH + d];
    }
    __syncthreads();

    const int tx = tid & 15;
    const int ty = tid >> 4;
    const int qi0 = ty * 4;
    const int kk0 = tx * 8;

    float sc[4][8];
    #pragma unroll
    for (int i = 0; i < 4; i++) {
        #pragma unroll
        for (int j = 0; j < 8; j++) {
            sc[i][j] = 0.0f;
        }
    }
    #pragma unroll 8
    for (int d = 0; d < 64; d++) {
        float4 a  = *(const float4*)&Qs[d * QS_STR + qi0];
        float4 b0 = *(const float4*)&Ks[d * KS_STR + kk0];
        float4 b1 = *(const float4*)&Ks[d * KS_STR + kk0 + 4];
        float av[4] = {a.x, a.y, a.z, a.w};
        float bv[8] = {b0.x, b0.y, b0.z, b0.w, b1.x, b1.y, b1.z, b1.w};
        #pragma unroll
        for (int i = 0; i < 4; i++) {
            #pragma unroll
            for (int j = 0; j < 8; j++) {
                sc[i][j] = fmaf(av[i], bv[j], sc[i][j]);
            }
        }
    }
    __syncthreads();   // scores in regs; safe to overwrite Qs/Ks with Ps

    #pragma unroll
    for (int i = 0; i < 4; i++) {
        #pragma unroll
        for (int j = 0; j < 8; j++) {
            int qi = qi0 + i;
            int kk = kk0 + j;
            int r  = kk - qi;
            int jg = i0 - 64 + kk;
            float val = NEGV;
            if (r >= 0 && r <= WIN && jg >= 0) {
                val = sc[i][j] * 0.125f + bias_s[r];
            }
            Ps[kk * PS_STR + qi] = val;
        }
    }
    __syncthreads();

    {
        const int warp = tid >> 5;
        const int lane = tid & 31;
        for (int rr = 0; rr < 8; rr++) {
            int qi = warp * 8 + rr;
            float v[4];
            float mx = -3.4e38f;
            #pragma unroll
            for (int t = 0; t < 4; t++) {
                v[t] = Ps[(lane + t * 32) * PS_STR + qi];
                mx = fmaxf(mx, v[t]);
            }
            #pragma unroll
            for (int o = 16; o > 0; o >>= 1) {
                mx = fmaxf(mx, __shfl_xor_sync(0xffffffffu, mx, o));
            }
            float sum = 0.0f;
            #pragma unroll
            for (int t = 0; t < 4; t++) {
                v[t] = expf(v[t] - mx);
                sum += v[t];
            }
            #pragma unroll
            for (int o = 16; o > 0; o >>= 1) {
                sum += __shfl_xor_sync(0xffffffffu, sum, o);
            }
            float inv = 1.0f / sum;
            #pragma unroll
            for (int t = 0; t < 4; t++) {
                Ps[(lane + t * 32) * PS_STR + qi] = v[t] * inv;
            }
        }
    }
    __syncthreads();

    for (int idx = tid; idx < 64 * 128; idx += 256) {
        int qi = idx >> 7;
        int slot = idx & 127;
        int i = i0 + qi;
        float val = 0.0f;
        if (i < WIN) {
            if (slot <= qi) {
                val = Ps[(slot + 64) * PS_STR + qi];
            }
        } else if (i >= S - WIN) {
            if (slot <= WIN) {
                val = Ps[(qi + slot) * PS_STR + qi];
            }
        }
        attn_w[((size_t)h * S + i) * 128 + slot] = val;
    }

    const int dk0 = tx * 4;
    float acc[4][4];
    #pragma unroll
    for (int i = 0; i < 4; i++) {
        #pragma unroll
        for (int j = 0; j < 4; j++) {
            acc[i][j] = 0.0f;
        }
    }
    #pragma unroll 4
    for (int kk = 0; kk < 128; kk++) {
        float4 p  = *(const float4*)&Ps[kk * PS_STR + qi0];
        float4 vv = *(const float4*)&Vs[kk * VS_STR + dk0];
        float pv[4] = {p.x, p.y, p.z, p.w};
        float vb[4] = {vv.x, vv.y, vv.z, vv.w};
        #pragma unroll
        for (int i = 0; i < 4; i++) {
            #pragma unroll
            for (int j = 0; j < 4; j++) {
                acc[i][j] = fmaf(pv[i], vb[j], acc[i][j]);
            }
        }
    }
    #pragma unroll
    for (int i = 0; i < 4; i++) {
        size_t base = (size_t)(i0 + qi0 + i) * DMODEL + h * DKH + dk0;
        __half hh[4];
        __half ll[4];
        #pragma unroll
        for (int j = 0; j < 4; j++) {
            float vv = acc[i][j];
            hh[j] = __float2half(vv);
            ll[j] = __float2half(vv - __half2float(hh[j]));
        }
        *(__half2*)(g_AOh + base)     = __halves2half2(hh[0], hh[1]);
        *(__half2*)(g_AOh + base + 2) = __halves2half2(hh[2], hh[3]);
        *(__half2*)(g_AOl + base)     = __halves2half2(ll[0], ll[1]);
        *(__half2*)(g_AOl + base + 2) = __halves2half2(ll[2], ll[3]);
    }
}

// ---------------- launch ----------------
extern "C" void kernel_launch(void* const* d_in, const int* in_sizes, int n_in,
                              void* d_out, int out_size) {
    const float* q  = (const float*)d_in[0];
    const float* k  = (const float*)d_in[1];
    const float* v  = (const float*)d_in[2];
    const float* Wq = (const float*)d_in[3];
    const float* Wk = (const float*)d_in[4];
    const float* Wv = (const float*)d_in[5];
    const float* Wo = (const float*)d_in[6];
    const float* bo = (const float*)d_in[7];

    float* out    = (float*)d_out;
    float* attn_w = out + (size_t)SD;

    __half* pxh;
    __half* pxl;
    __half* pwh;
    __half* paoh;
    __half* paol;
    float* pqkv;
    cudaGetSymbolAddress((void**)&pxh,  g_xh);
    cudaGetSymbolAddress((void**)&pxl,  g_xl);
    cudaGetSymbolAddress((void**)&pwh,  g_Wh);
    cudaGetSymbolAddress((void**)&pqkv, g_QKV);
    cudaGetSymbolAddress((void**)&paoh, g_AOh);
    cudaGetSymbolAddress((void**)&paol, g_AOl);

    const int SMEM_ATTN = (64*QS_STR + 64*KS_STR + 128*VS_STR + 72) * (int)sizeof(float);
    cudaFuncSetAttribute(local_attn, cudaFuncAttributeMaxDynamicSharedMemorySize, SMEM_ATTN);
    cudaFuncSetAttribute(gemm128x64, cudaFuncAttributeMaxDynamicSharedMemorySize, SMEM_GEMM);

    convert_split<<<4096, 256>>>(q, k, v, Wq, Wk, Wv, Wo);

    // QKV projections
    gemm128x64<<<dim3(DMODEL/64, S/128, 3), 256, SMEM_GEMM>>>(
        pxh, pxl, pwh, pqkv, nullptr);

    local_attn<<<dim3(S/64, NH), 256, SMEM_ATTN>>>(pqkv, pqkv + SD, pqkv + 2*SD, attn_w);

    // O-projection
    gemm128x64<<<dim3(DMODEL/64, S/128, 1), 256, SMEM_GEMM>>>(
        paoh, paol, pwh + 3*DD, out, bo);
}

// round 9
// speedup vs baseline: 1.2718x; 1.0488x over previous
#include <cuda_runtime.h>
#include <cuda_fp16.h>
#include <cstdint>
#include <math.h>

#define S 2048
#define DMODEL 512
#define NH 8
#define DKH 64
#define WIN 64
#define NEGV -1000000000.0f
#define SD (S*DMODEL)
#define DD (DMODEL*DMODEL)

#define QS_STR 68
#define KS_STR 132
#define VS_STR 68
#define PS_STR 68

#define LDA 40

typedef unsigned int u32;

// ---------------- device scratch (allocation-free rule) ----------------
__device__ __half g_xh[3*SD];     // activations hi
__device__ __half g_xl[3*SD];     // activations lo
__device__ __half g_Wh[4*DD];     // weights (fp16)
__device__ float  g_QKV[3*SD];
__device__ __half g_AOh[SD];
__device__ __half g_AOl[SD];

// ---------------- fp32 -> fp16 split (A: hi/lo, W: hi only) ----------------
__global__ void __launch_bounds__(256) convert_split(
    const float* __restrict__ q, const float* __restrict__ k, const float* __restrict__ v,
    const float* __restrict__ Wq, const float* __restrict__ Wk,
    const float* __restrict__ Wv, const float* __restrict__ Wo)
{
    const int SD4 = SD/4;
    const int DD4 = DD/4;
    int idx = blockIdx.x * 256 + threadIdx.x;
    if (idx < 3*SD4) {
        int r = idx / SD4;
        size_t e = (size_t)(idx - r*SD4) * 4;
        const float* src = (r == 0 ? q : (r == 1 ? k : v)) + e;
        __half* dh = g_xh + (size_t)r*SD + e;
        __half* dl = g_xl + (size_t)r*SD + e;
        float4 f = *(const float4*)src;
        __half h0 = __float2half(f.x);
        __half h1 = __float2half(f.y);
        __half h2 = __float2half(f.z);
        __half h3 = __float2half(f.w);
        __half l0 = __float2half(f.x - __half2float(h0));
        __half l1 = __float2half(f.y - __half2float(h1));
        __half l2 = __float2half(f.z - __half2float(h2));
        __half l3 = __float2half(f.w - __half2float(h3));
        *(__half2*)(dh)     = __halves2half2(h0, h1);
        *(__half2*)(dh + 2) = __halves2half2(h2, h3);
        *(__half2*)(dl)     = __halves2half2(l0, l1);
        *(__half2*)(dl + 2) = __halves2half2(l2, l3);
    } else {
        int j = idx - 3*SD4;
        int r = j / DD4;
        size_t e = (size_t)(j - r*DD4) * 4;
        const float* src = (r == 0 ? Wq : (r == 1 ? Wk : (r == 2 ? Wv : Wo))) + e;
        __half* dh = g_Wh + (size_t)r*DD + e;
        float4 f = *(const float4*)src;
        *(__half2*)(dh)     = __halves2half2(__float2half(f.x), __float2half(f.y));
        *(__half2*)(dh + 2) = __halves2half2(__float2half(f.z), __float2half(f.w));
    }
}

// ---------------- tensor-core GEMM helpers ----------------
__device__ __forceinline__ void ldsm4(u32* r, u32 a) {
    asm volatile("ldmatrix.sync.aligned.m8n8.x4.shared.b16 {%0,%1,%2,%3}, [%4];"
        : "=r"(r[0]), "=r"(r[1]), "=r"(r[2]), "=r"(r[3]) : "r"(a));
}
__device__ __forceinline__ void mma_fp16(float* c, const u32* a, const u32* b) {
    asm volatile("mma.sync.aligned.m16n8k16.row.col.f32.f16.f16.f32 "
        "{%0,%1,%2,%3},{%4,%5,%6,%7},{%8,%9},{%0,%1,%2,%3};"
        : "+f"(c[0]), "+f"(c[1]), "+f"(c[2]), "+f"(c[3])
        : "r"(a[0]), "r"(a[1]), "r"(a[2]), "r"(a[3]), "r"(b[0]), "r"(b[1]));
}
__device__ __forceinline__ void cp16(u32 dst, const void* src) {
    asm volatile("cp.async.cg.shared.global [%0], [%1], 16;" :: "r"(dst), "l"(src));
}
__device__ __forceinline__ void cp_commit() {
    asm volatile("cp.async.commit_group;");
}

// Per-stage byte sizes; 2-stage double buffer. 64x64 tile -> A stage = 64 rows.
#define STG_A (64*LDA*2)
#define STG_W (64*LDA*2)
#define SMEM_GEMM (2*(2*STG_A + STG_W))

// C[M,N] = A[M,K] @ W[N,K]^T (+bias). fp16 2-term: Ah*Wh + Al*Wh.
// Tile 64x64, BK=32, double-buffered cp.async, 3 CTAs/SM for latency hiding.
__global__ void __launch_bounds__(256, 3) gemm64x64(
    const __half* __restrict__ Ah_, const __half* __restrict__ Al_,
    const __half* __restrict__ Wh_,
    float* __restrict__ C, const float* __restrict__ bias)
{
    extern __shared__ __align__(16) __half dsm[];

    const size_t za = (size_t)blockIdx.z * SD;
    const size_t zw = (size_t)blockIdx.z * DD;
    const int tid = threadIdx.x;
    const int m_base = blockIdx.y * 64;
    const int n_base = blockIdx.x * 64;

    const int a_row = tid >> 2;          // 0..63
    const int a_col = (tid & 3) * 8;     // 0,8,16,24

    const int lane = tid & 31;
    const int wid = tid >> 5;
    const int warp_m = wid >> 1;         // 0..3  (16 rows each)
    const int warp_n = wid & 1;          // 0..1  (32 cols each)
    const int lrow = (lane & 7) + ((lane >> 3) & 1) * 8;
    const int lcol = (lane >> 4) * 8;

    const u32 base = (u32)__cvta_generic_to_shared(dsm);
    const u32 bAh = base;
    const u32 bAl = base + 2*STG_A;
    const u32 bWh = base + 4*STG_A;

    const __half* gA = Ah_ + za + (size_t)(m_base + a_row) * DMODEL + a_col;
    const __half* gL = Al_ + za + (size_t)(m_base + a_row) * DMODEL + a_col;
    const __half* gW = Wh_ + zw + (size_t)(n_base + a_row) * DMODEL + a_col;
    float* Cz = C + za;

    const u32 aoff = (u32)((a_row * LDA + a_col) * 2);

    float acc[4][4];
    #pragma unroll
    for (int ni = 0; ni < 4; ni++) {
        #pragma unroll
        for (int t = 0; t < 4; t++) {
            acc[ni][t] = 0.0f;
        }
    }

    // prologue: stage 0
    {
        cp16(bAh + aoff, gA);
        cp16(bAl + aoff, gL);
        cp16(bWh + aoff, gW);
        cp_commit();
    }

    for (int s = 0; s < 16; s++) {
        const u32 bufA = (u32)(s & 1) * STG_A;
        const u32 bufW = (u32)(s & 1) * STG_W;

        if (s < 15) {
            int k0 = (s + 1) * 32;
            u32 nbA = (u32)((s + 1) & 1) * STG_A;
            u32 nbW = (u32)((s + 1) & 1) * STG_W;
            cp16(bAh + nbA + aoff, gA + k0);
            cp16(bAl + nbA + aoff, gL + k0);
            cp16(bWh + nbW + aoff, gW + k0);
            cp_commit();
            asm volatile("cp.async.wait_group 1;");
        } else {
            asm volatile("cp.async.wait_group 0;");
        }
        __syncthreads();

        #pragma unroll
        for (int kb = 0; kb < 32; kb += 16) {
            u32 ah[4];
            u32 al[4];
            u32 bh[4][2];
            {
                u32 off = bufA + (u32)(((warp_m * 16 + lrow) * LDA + kb + lcol) * 2);
                ldsm4(ah, bAh + off);
                ldsm4(al, bAl + off);
            }
            #pragma unroll
            for (int g2 = 0; g2 < 2; g2++) {
                u32 off = bufW + (u32)(((warp_n * 32 + g2 * 16 + lrow) * LDA + kb + lcol) * 2);
                u32 r0[4];
                ldsm4(r0, bWh + off);
                bh[g2*2][0]   = r0[0];
                bh[g2*2+1][0] = r0[1];
                bh[g2*2][1]   = r0[2];
                bh[g2*2+1][1] = r0[3];
            }
            #pragma unroll
            for (int ni = 0; ni < 4; ni++) {
                mma_fp16(acc[ni], ah, bh[ni]);
                mma_fp16(acc[ni], al, bh[ni]);
            }
        }
        __syncthreads();
    }

    const int qr = lane >> 2;
    const int qc = (lane & 3) * 2;
    {
        int m0 = m_base + warp_m * 16 + qr;
        #pragma unroll
        for (int ni = 0; ni < 4; ni++) {
            int n = n_base + warp_n * 32 + ni * 8 + qc;
            float b0 = 0.0f;
            float b1 = 0.0f;
            if (bias) {
                b0 = bias[n];
                b1 = bias[n + 1];
            }
            float2 v0 = make_float2(acc[ni][0] + b0, acc[ni][1] + b1);
            float2 v1 = make_float2(acc[ni][2] + b0, acc[ni][3] + b1);
            *(float2*)(Cz + (size_t)m0 * DMODEL + n) = v0;
            *(float2*)(Cz + (size_t)(m0 + 8) * DMODEL + n) = v1;
        }
    }
}

// ---------------- windowed attention ----------------
__global__ void __launch_bounds__(256) local_attn(
    const float* __restrict__ Q, const float* __restrict__ K,
    const float* __restrict__ V, float* __restrict__ attn_w)
{
    extern __shared__ __align__(16) float sm[];
    float* Qs = sm;
    float* Ks = sm + 64*QS_STR;
    float* Vs = sm + 64*QS_STR + 64*KS_STR;
    float* bias_s = Vs + 128*VS_STR;
    float* Ps = sm;   // aliases Qs+Ks after scores move to registers

    const int h  = blockIdx.y;
    const int i0 = blockIdx.x * 64;
    const int tid = threadIdx.x;

    if (tid <= WIN) {
        bias_s[tid] = 0.1f * expf(-0.1f * (float)(WIN - tid));
    }

    for (int idx = tid; idx < 64 * 64; idx += 256) {
        int qi = idx >> 6;
        int d  = idx & 63;
        Qs[d * QS_STR + qi] = Q[(size_t)(i0 + qi) * DMODEL + h * DKH + d];
    }
    for (int idx = tid; idx < 128 * 64; idx += 256) {
        int kk = idx >> 6;
        int d  = idx & 63;
        int j = i0 - 64 + kk;
        int jc = (j < 0) ? 0 : j;
        Ks[d * KS_STR + kk] = K[(size_t)jc * DMODEL + h * DKH + d];
        Vs[kk * VS_STR + d] = V[(size_t)jc * DMODEL + h * DKH + d];
    }
    __syncthreads();

    const int tx = tid & 15;
    const int ty = tid >> 4;
    const int qi0 = ty * 4;
    const int kk0 = tx * 8;

    float sc[4][8];
    #pragma unroll
    for (int i = 0; i < 4; i++) {
        #pragma unroll
        for (int j = 0; j < 8; j++) {
            sc[i][j] = 0.0f;
        }
    }
    #pragma unroll 8
    for (int d = 0; d < 64; d++) {
        float4 a  = *(const float4*)&Qs[d * QS_STR + qi0];
        float4 b0 = *(const float4*)&Ks[d * KS_STR + kk0];
        float4 b1 = *(const float4*)&Ks[d * KS_STR + kk0 + 4];
        float av[4] = {a.x, a.y, a.z, a.w};
        float bv[8] = {b0.x, b0.y, b0.z, b0.w, b1.x, b1.y, b1.z, b1.w};
        #pragma unroll
        for (int i = 0; i < 4; i++) {
            #pragma unroll
            for (int j = 0; j < 8; j++) {
                sc[i][j] = fmaf(av[i], bv[j], sc[i][j]);
            }
        }
    }
    __syncthreads();   // scores in regs; safe to overwrite Qs/Ks with Ps

    #pragma unroll
    for (int i = 0; i < 4; i++) {
        #pragma unroll
        for (int j = 0; j < 8; j++) {
            int qi = qi0 + i;
            int kk = kk0 + j;
            int r  = kk - qi;
            int jg = i0 - 64 + kk;
            float val = NEGV;
            if (r >= 0 && r <= WIN && jg >= 0) {
                val = sc[i][j] * 0.125f + bias_s[r];
            }
            Ps[kk * PS_STR + qi] = val;
        }
    }
    __syncthreads();

    {
        const int warp = tid >> 5;
        const int lane = tid & 31;
        for (int rr = 0; rr < 8; rr++) {
            int qi = warp * 8 + rr;
            float v[4];
            float mx = -3.4e38f;
            #pragma unroll
            for (int t = 0; t < 4; t++) {
                v[t] = Ps[(lane + t * 32) * PS_STR + qi];
                mx = fmaxf(mx, v[t]);
            }
            #pragma unroll
            for (int o = 16; o > 0; o >>= 1) {
                mx = fmaxf(mx, __shfl_xor_sync(0xffffffffu, mx, o));
            }
            float sum = 0.0f;
            #pragma unroll
            for (int t = 0; t < 4; t++) {
                v[t] = expf(v[t] - mx);
                sum += v[t];
            }
            #pragma unroll
            for (int o = 16; o > 0; o >>= 1) {
                sum += __shfl_xor_sync(0xffffffffu, sum, o);
            }
            float inv = 1.0f / sum;
            #pragma unroll
            for (int t = 0; t < 4; t++) {
                Ps[(lane + t * 32) * PS_STR + qi] = v[t] * inv;
            }
        }
    }
    __syncthreads();

    for (int idx = tid; idx < 64 * 128; idx += 256) {
        int qi = idx >> 7;
        int slot = idx & 127;
        int i = i0 + qi;
        float val = 0.0f;
        if (i < WIN) {
            if (slot <= qi) {
                val = Ps[(slot + 64) * PS_STR + qi];
            }
        } else if (i >= S - WIN) {
            if (slot <= WIN) {
                val = Ps[(qi + slot) * PS_STR + qi];
            }
        }
        attn_w[((size_t)h * S + i) * 128 + slot] = val;
    }

    const int dk0 = tx * 4;
    float acc[4][4];
    #pragma unroll
    for (int i = 0; i < 4; i++) {
        #pragma unroll
        for (int j = 0; j < 4; j++) {
            acc[i][j] = 0.0f;
        }
    }
    #pragma unroll 4
    for (int kk = 0; kk < 128; kk++) {
        float4 p  = *(const float4*)&Ps[kk * PS_STR + qi0];
        float4 vv = *(const float4*)&Vs[kk * VS_STR + dk0];
        float pv[4] = {p.x, p.y, p.z, p.w};
        float vb[4] = {vv.x, vv.y, vv.z, vv.w};
        #pragma unroll
        for (int i = 0; i < 4; i++) {
            #pragma unroll
            for (int j = 0; j < 4; j++) {
                acc[i][j] = fmaf(pv[i], vb[j], acc[i][j]);
            }
        }
    }
    #pragma unroll
    for (int i = 0; i < 4; i++) {
        size_t base = (size_t)(i0 + qi0 + i) * DMODEL + h * DKH + dk0;
        __half hh[4];
        __half ll[4];
        #pragma unroll
        for (int j = 0; j < 4; j++) {
            float vv = acc[i][j];
            hh[j] = __float2half(vv);
            ll[j] = __float2half(vv - __half2float(hh[j]));
        }
        *(__half2*)(g_AOh + base)     = __halves2half2(hh[0], hh[1]);
        *(__half2*)(g_AOh + base + 2) = __halves2half2(hh[2], hh[3]);
        *(__half2*)(g_AOl + base)     = __halves2half2(ll[0], ll[1]);
        *(__half2*)(g_AOl + base + 2) = __halves2half2(ll[2], ll[3]);
    }
}

// ---------------- launch ----------------
extern "C" void kernel_launch(void* const* d_in, const int* in_sizes, int n_in,
                              void* d_out, int out_size) {
    const float* q  = (const float*)d_in[0];
    const float* k  = (const float*)d_in[1];
    const float* v  = (const float*)d_in[2];
    const float* Wq = (const float*)d_in[3];
    const float* Wk = (const float*)d_in[4];
    const float* Wv = (const float*)d_in[5];
    const float* Wo = (const float*)d_in[6];
    const float* bo = (const float*)d_in[7];

    float* out    = (float*)d_out;
    float* attn_w = out + (size_t)SD;

    __half* pxh;
    __half* pxl;
    __half* pwh;
    __half* paoh;
    __half* paol;
    float* pqkv;
    cudaGetSymbolAddress((void**)&pxh,  g_xh);
    cudaGetSymbolAddress((void**)&pxl,  g_xl);
    cudaGetSymbolAddress((void**)&pwh,  g_Wh);
    cudaGetSymbolAddress((void**)&pqkv, g_QKV);
    cudaGetSymbolAddress((void**)&paoh, g_AOh);
    cudaGetSymbolAddress((void**)&paol, g_AOl);

    const int SMEM_ATTN = (64*QS_STR + 64*KS_STR + 128*VS_STR + 72) * (int)sizeof(float);
    cudaFuncSetAttribute(local_attn, cudaFuncAttributeMaxDynamicSharedMemorySize, SMEM_ATTN);
    cudaFuncSetAttribute(gemm64x64, cudaFuncAttributeMaxDynamicSharedMemorySize, SMEM_GEMM);

    convert_split<<<4096, 256>>>(q, k, v, Wq, Wk, Wv, Wo);

    // QKV projections (grid 8 x 32 x 3 = 768 CTAs)
    gemm64x64<<<dim3(DMODEL/64, S/64, 3), 256, SMEM_GEMM>>>(
        pxh, pxl, pwh, pqkv, nullptr);

    local_attn<<<dim3(S/64, NH), 256, SMEM_ATTN>>>(pqkv, pqkv + SD, pqkv + 2*SD, attn_w);

    // O-projection (grid 8 x 32 = 256 CTAs)
    gemm64x64<<<dim3(DMODEL/64, S/64, 1), 256, SMEM_GEMM>>>(
        paoh, paol, pwh + 3*DD, out, bo);
}

// round 10
// speedup vs baseline: 1.4652x; 1.1521x over previous
#include <cuda_runtime.h>
#include <cuda_fp16.h>
#include <cstdint>
#include <math.h>

#define S 2048
#define DMODEL 512
#define NH 8
#define DKH 64
#define WIN 64
#define NEGV -1000000000.0f
#define SD (S*DMODEL)
#define DD (DMODEL*DMODEL)

#define PS_STR 68
#define VS_STR 68
#define QH_STR 72

#define LDA 40

typedef unsigned int u32;

// ---------------- device scratch (allocation-free rule) ----------------
__device__ __half g_xh[3*SD];     // activations hi
__device__ __half g_xl[3*SD];     // activations lo
__device__ __half g_Wh[4*DD];     // weights (fp16)
__device__ float  g_QKV[3*SD];
__device__ __half g_AOh[SD];
__device__ __half g_AOl[SD];

// ---------------- fp32 -> fp16 split (A: hi/lo, W: hi only) ----------------
__global__ void __launch_bounds__(256) convert_split(
    const float* __restrict__ q, const float* __restrict__ k, const float* __restrict__ v,
    const float* __restrict__ Wq, const float* __restrict__ Wk,
    const float* __restrict__ Wv, const float* __restrict__ Wo)
{
    const int SD4 = SD/4;
    const int DD4 = DD/4;
    int idx = blockIdx.x * 256 + threadIdx.x;
    if (idx < 3*SD4) {
        int r = idx / SD4;
        size_t e = (size_t)(idx - r*SD4) * 4;
        const float* src = (r == 0 ? q : (r == 1 ? k : v)) + e;
        __half* dh = g_xh + (size_t)r*SD + e;
        __half* dl = g_xl + (size_t)r*SD + e;
        float4 f = *(const float4*)src;
        __half h0 = __float2half(f.x);
        __half h1 = __float2half(f.y);
        __half h2 = __float2half(f.z);
        __half h3 = __float2half(f.w);
        __half l0 = __float2half(f.x - __half2float(h0));
        __half l1 = __float2half(f.y - __half2float(h1));
        __half l2 = __float2half(f.z - __half2float(h2));
        __half l3 = __float2half(f.w - __half2float(h3));
        *(__half2*)(dh)     = __halves2half2(h0, h1);
        *(__half2*)(dh + 2) = __halves2half2(h2, h3);
        *(__half2*)(dl)     = __halves2half2(l0, l1);
        *(__half2*)(dl + 2) = __halves2half2(l2, l3);
    } else {
        int j = idx - 3*SD4;
        int r = j / DD4;
        size_t e = (size_t)(j - r*DD4) * 4;
        const float* src = (r == 0 ? Wq : (r == 1 ? Wk : (r == 2 ? Wv : Wo))) + e;
        __half* dh = g_Wh + (size_t)r*DD + e;
        float4 f = *(const float4*)src;
        *(__half2*)(dh)     = __halves2half2(__float2half(f.x), __float2half(f.y));
        *(__half2*)(dh + 2) = __halves2half2(__float2half(f.z), __float2half(f.w));
    }
}

// ---------------- tensor-core helpers ----------------
__device__ __forceinline__ void ldsm4(u32* r, u32 a) {
    asm volatile("ldmatrix.sync.aligned.m8n8.x4.shared.b16 {%0,%1,%2,%3}, [%4];"
        : "=r"(r[0]), "=r"(r[1]), "=r"(r[2]), "=r"(r[3]) : "r"(a));
}
__device__ __forceinline__ void mma_fp16(float* c, const u32* a, const u32* b) {
    asm volatile("mma.sync.aligned.m16n8k16.row.col.f32.f16.f16.f32 "
        "{%0,%1,%2,%3},{%4,%5,%6,%7},{%8,%9},{%0,%1,%2,%3};"
        : "+f"(c[0]), "+f"(c[1]), "+f"(c[2]), "+f"(c[3])
        : "r"(a[0]), "r"(a[1]), "r"(a[2]), "r"(a[3]), "r"(b[0]), "r"(b[1]));
}
__device__ __forceinline__ void cp16(u32 dst, const void* src) {
    asm volatile("cp.async.cg.shared.global [%0], [%1], 16;" :: "r"(dst), "l"(src));
}
__device__ __forceinline__ void cp_commit() {
    asm volatile("cp.async.commit_group;");
}

// ---------------- GEMM (unchanged from round 9) ----------------
#define STG_A (64*LDA*2)
#define STG_W (64*LDA*2)
#define SMEM_GEMM (2*(2*STG_A + STG_W))

__global__ void __launch_bounds__(256, 3) gemm64x64(
    const __half* __restrict__ Ah_, const __half* __restrict__ Al_,
    const __half* __restrict__ Wh_,
    float* __restrict__ C, const float* __restrict__ bias)
{
    extern __shared__ __align__(16) __half dsm[];

    const size_t za = (size_t)blockIdx.z * SD;
    const size_t zw = (size_t)blockIdx.z * DD;
    const int tid = threadIdx.x;
    const int m_base = blockIdx.y * 64;
    const int n_base = blockIdx.x * 64;

    const int a_row = tid >> 2;
    const int a_col = (tid & 3) * 8;

    const int lane = tid & 31;
    const int wid = tid >> 5;
    const int warp_m = wid >> 1;
    const int warp_n = wid & 1;
    const int lrow = (lane & 7) + ((lane >> 3) & 1) * 8;
    const int lcol = (lane >> 4) * 8;

    const u32 base = (u32)__cvta_generic_to_shared(dsm);
    const u32 bAh = base;
    const u32 bAl = base + 2*STG_A;
    const u32 bWh = base + 4*STG_A;

    const __half* gA = Ah_ + za + (size_t)(m_base + a_row) * DMODEL + a_col;
    const __half* gL = Al_ + za + (size_t)(m_base + a_row) * DMODEL + a_col;
    const __half* gW = Wh_ + zw + (size_t)(n_base + a_row) * DMODEL + a_col;
    float* Cz = C + za;

    const u32 aoff = (u32)((a_row * LDA + a_col) * 2);

    float acc[4][4];
    #pragma unroll
    for (int ni = 0; ni < 4; ni++) {
        #pragma unroll
        for (int t = 0; t < 4; t++) {
            acc[ni][t] = 0.0f;
        }
    }

    {
        cp16(bAh + aoff, gA);
        cp16(bAl + aoff, gL);
        cp16(bWh + aoff, gW);
        cp_commit();
    }

    for (int s = 0; s < 16; s++) {
        const u32 bufA = (u32)(s & 1) * STG_A;
        const u32 bufW = (u32)(s & 1) * STG_W;

        if (s < 15) {
            int k0 = (s + 1) * 32;
            u32 nbA = (u32)((s + 1) & 1) * STG_A;
            u32 nbW = (u32)((s + 1) & 1) * STG_W;
            cp16(bAh + nbA + aoff, gA + k0);
            cp16(bAl + nbA + aoff, gL + k0);
            cp16(bWh + nbW + aoff, gW + k0);
            cp_commit();
            asm volatile("cp.async.wait_group 1;");
        } else {
            asm volatile("cp.async.wait_group 0;");
        }
        __syncthreads();

        #pragma unroll
        for (int kb = 0; kb < 32; kb += 16) {
            u32 ah[4];
            u32 al[4];
            u32 bh[4][2];
            {
                u32 off = bufA + (u32)(((warp_m * 16 + lrow) * LDA + kb + lcol) * 2);
                ldsm4(ah, bAh + off);
                ldsm4(al, bAl + off);
            }
            #pragma unroll
            for (int g2 = 0; g2 < 2; g2++) {
                u32 off = bufW + (u32)(((warp_n * 32 + g2 * 16 + lrow) * LDA + kb + lcol) * 2);
                u32 r0[4];
                ldsm4(r0, bWh + off);
                bh[g2*2][0]   = r0[0];
                bh[g2*2+1][0] = r0[1];
                bh[g2*2][1]   = r0[2];
                bh[g2*2+1][1] = r0[3];
            }
            #pragma unroll
            for (int ni = 0; ni < 4; ni++) {
                mma_fp16(acc[ni], ah, bh[ni]);
                mma_fp16(acc[ni], al, bh[ni]);
            }
        }
        __syncthreads();
    }

    const int qr = lane >> 2;
    const int qc = (lane & 3) * 2;
    {
        int m0 = m_base + warp_m * 16 + qr;
        #pragma unroll
        for (int ni = 0; ni < 4; ni++) {
            int n = n_base + warp_n * 32 + ni * 8 + qc;
            float b0 = 0.0f;
            float b1 = 0.0f;
            if (bias) {
                b0 = bias[n];
                b1 = bias[n + 1];
            }
            float2 v0 = make_float2(acc[ni][0] + b0, acc[ni][1] + b1);
            float2 v1 = make_float2(acc[ni][2] + b0, acc[ni][3] + b1);
            *(float2*)(Cz + (size_t)m0 * DMODEL + n) = v0;
            *(float2*)(Cz + (size_t)(m0 + 8) * DMODEL + n) = v1;
        }
    }
}

// ---------------- windowed attention (scores via fp16 MMA) ----------------
// smem layout (bytes):
//   [0, 9216)          Qh  [64][72] half
//   [9216, 18432)      Ql  [64][72] half
//   [18432, 36864)     Ks  [128][72] half
//   [0, 34816)         Ps  [128][68] float  (aliases Qh/Ql/Ks after MMA)
//   [36864, 71680)     Vs  [128][68] float
//   [71680, 71968)     bias_s [65] float
#define SMEM_ATTN 71968

__global__ void __launch_bounds__(256, 2) local_attn(
    const float* __restrict__ Q, const float* __restrict__ K,
    const float* __restrict__ V, float* __restrict__ attn_w)
{
    extern __shared__ __align__(16) char smc[];
    __half* Qh = (__half*)(smc);
    __half* Ql = (__half*)(smc + 9216);
    __half* Ks = (__half*)(smc + 18432);
    float*  Ps = (float*)(smc);
    float*  Vs = (float*)(smc + 36864);
    float*  bias_s = (float*)(smc + 71680);

    const int h  = blockIdx.y;
    const int i0 = blockIdx.x * 64;
    const int tid = threadIdx.x;

    if (tid <= WIN) {
        bias_s[tid] = 0.1f * expf(-0.1f * (float)(WIN - tid));
    }

    // Q tile: fp16 hi/lo, row-major [qi][d]
    for (int idx = tid; idx < 64 * 64; idx += 256) {
        int qi = idx >> 6;
        int d  = idx & 63;
        float qv = Q[(size_t)(i0 + qi) * DMODEL + h * DKH + d];
        __half hh = __float2half(qv);
        Qh[qi * QH_STR + d] = hh;
        Ql[qi * QH_STR + d] = __float2half(qv - __half2float(hh));
    }
    // K tile fp16 [kk][d]; V tile fp32 [kk][dk]
    for (int idx = tid; idx < 128 * 64; idx += 256) {
        int kk = idx >> 6;
        int d  = idx & 63;
        int j = i0 - 64 + kk;
        int jc = (j < 0) ? 0 : j;
        Ks[kk * QH_STR + d] = __float2half(K[(size_t)jc * DMODEL + h * DKH + d]);
        Vs[kk * VS_STR + d] = V[(size_t)jc * DMODEL + h * DKH + d];
    }
    __syncthreads();

    const int lane = tid & 31;
    const int wid  = tid >> 5;
    const int warp_m = wid >> 1;   // 0..3 -> 16 q-rows each
    const int warp_n = wid & 1;    // 0..1 -> 64 kk-cols each
    const int lrow = (lane & 7) + ((lane >> 3) & 1) * 8;
    const int lcol = (lane >> 4) * 8;

    const u32 bQh = (u32)__cvta_generic_to_shared(Qh);
    const u32 bQl = (u32)__cvta_generic_to_shared(Ql);
    const u32 bKs = (u32)__cvta_generic_to_shared(Ks);

    float sc[8][4];
    #pragma unroll
    for (int nt = 0; nt < 8; nt++) {
        #pragma unroll
        for (int t = 0; t < 4; t++) {
            sc[nt][t] = 0.0f;
        }
    }

    #pragma unroll
    for (int kc = 0; kc < 64; kc += 16) {
        u32 ah[4];
        u32 al[4];
        u32 bf[8][2];
        {
            u32 off = (u32)(((warp_m * 16 + lrow) * QH_STR + kc + lcol) * 2);
            ldsm4(ah, bQh + off);
            ldsm4(al, bQl + off);
        }
        #pragma unroll
        for (int g = 0; g < 4; g++) {
            u32 off = (u32)(((warp_n * 64 + g * 16 + lrow) * QH_STR + kc + lcol) * 2);
            u32 r0[4];
            ldsm4(r0, bKs + off);
            bf[g*2][0]   = r0[0];
            bf[g*2+1][0] = r0[1];
            bf[g*2][1]   = r0[2];
            bf[g*2+1][1] = r0[3];
        }
        #pragma unroll
        for (int nt = 0; nt < 8; nt++) {
            mma_fp16(sc[nt], ah, bf[nt]);
            mma_fp16(sc[nt], al, bf[nt]);
        }
    }
    __syncthreads();   // all ldsm reads of Qh/Ql/Ks done -> Ps may overwrite

    // mask + decay bias, store transposed Ps[kk][qi]
    {
        const int qr = lane >> 2;
        const int qc = (lane & 3) * 2;
        #pragma unroll
        for (int nt = 0; nt < 8; nt++) {
            #pragma unroll
            for (int t = 0; t < 4; t++) {
                int kk = warp_n * 64 + nt * 8 + qc + (t & 1);
                int qi = warp_m * 16 + qr + (t >> 1) * 8;
                int r  = kk - qi;
                int jg = i0 - 64 + kk;
                float val = NEGV;
                if (r >= 0 && r <= WIN && jg >= 0) {
                    val = sc[nt][t] * 0.125f + bias_s[r];
                }
                Ps[kk * PS_STR + qi] = val;
            }
        }
    }
    __syncthreads();

    {   // softmax over kk per row qi
        const int warp = tid >> 5;
        for (int rr = 0; rr < 8; rr++) {
            int qi = warp * 8 + rr;
            float v[4];
            float mx = -3.4e38f;
            #pragma unroll
            for (int t = 0; t < 4; t++) {
                v[t] = Ps[(lane + t * 32) * PS_STR + qi];
                mx = fmaxf(mx, v[t]);
            }
            #pragma unroll
            for (int o = 16; o > 0; o >>= 1) {
                mx = fmaxf(mx, __shfl_xor_sync(0xffffffffu, mx, o));
            }
            float sum = 0.0f;
            #pragma unroll
            for (int t = 0; t < 4; t++) {
                v[t] = expf(v[t] - mx);
                sum += v[t];
            }
            #pragma unroll
            for (int o = 16; o > 0; o >>= 1) {
                sum += __shfl_xor_sync(0xffffffffu, sum, o);
            }
            float inv = 1.0f / sum;
            #pragma unroll
            for (int t = 0; t < 4; t++) {
                Ps[(lane + t * 32) * PS_STR + qi] = v[t] * inv;
            }
        }
    }
    __syncthreads();

    for (int idx = tid; idx < 64 * 128; idx += 256) {
        int qi = idx >> 7;
        int slot = idx & 127;
        int i = i0 + qi;
        float val = 0.0f;
        if (i < WIN) {
            if (slot <= qi) {
                val = Ps[(slot + 64) * PS_STR + qi];
            }
        } else if (i >= S - WIN) {
            if (slot <= WIN) {
                val = Ps[(qi + slot) * PS_STR + qi];
            }
        }
        attn_w[((size_t)h * S + i) * 128 + slot] = val;
    }

    // PV (fp32 FMA, unchanged)
    const int tx = tid & 15;
    const int ty = tid >> 4;
    const int qi0 = ty * 4;
    const int dk0 = tx * 4;
    float acc[4][4];
    #pragma unroll
    for (int i = 0; i < 4; i++) {
        #pragma unroll
        for (int j = 0; j < 4; j++) {
            acc[i][j] = 0.0f;
        }
    }
    #pragma unroll 4
    for (int kk = 0; kk < 128; kk++) {
        float4 p  = *(const float4*)&Ps[kk * PS_STR + qi0];
        float4 vv = *(const float4*)&Vs[kk * VS_STR + dk0];
        float pv[4] = {p.x, p.y, p.z, p.w};
        float vb[4] = {vv.x, vv.y, vv.z, vv.w};
        #pragma unroll
        for (int i = 0; i < 4; i++) {
            #pragma unroll
            for (int j = 0; j < 4; j++) {
                acc[i][j] = fmaf(pv[i], vb[j], acc[i][j]);
            }
        }
    }
    #pragma unroll
    for (int i = 0; i < 4; i++) {
        size_t base = (size_t)(i0 + qi0 + i) * DMODEL + h * DKH + dk0;
        __half hh[4];
        __half ll[4];
        #pragma unroll
        for (int j = 0; j < 4; j++) {
            float vv = acc[i][j];
            hh[j] = __float2half(vv);
            ll[j] = __float2half(vv - __half2float(hh[j]));
        }
        *(__half2*)(g_AOh + base)     = __halves2half2(hh[0], hh[1]);
        *(__half2*)(g_AOh + base + 2) = __halves2half2(hh[2], hh[3]);
        *(__half2*)(g_AOl + base)     = __halves2half2(ll[0], ll[1]);
        *(__half2*)(g_AOl + base + 2) = __halves2half2(ll[2], ll[3]);
    }
}

// ---------------- launch ----------------
extern "C" void kernel_launch(void* const* d_in, const int* in_sizes, int n_in,
                              void* d_out, int out_size) {
    const float* q  = (const float*)d_in[0];
    const float* k  = (const float*)d_in[1];
    const float* v  = (const float*)d_in[2];
    const float* Wq = (const float*)d_in[3];
    const float* Wk = (const float*)d_in[4];
    const float* Wv = (const float*)d_in[5];
    const float* Wo = (const float*)d_in[6];
    const float* bo = (const float*)d_in[7];

    float* out    = (float*)d_out;
    float* attn_w = out + (size_t)SD;

    __half* pxh;
    __half* pxl;
    __half* pwh;
    __half* paoh;
    __half* paol;
    float* pqkv;
    cudaGetSymbolAddress((void**)&pxh,  g_xh);
    cudaGetSymbolAddress((void**)&pxl,  g_xl);
    cudaGetSymbolAddress((void**)&pwh,  g_Wh);
    cudaGetSymbolAddress((void**)&pqkv, g_QKV);
    cudaGetSymbolAddress((void**)&paoh, g_AOh);
    cudaGetSymbolAddress((void**)&paol, g_AOl);

    cudaFuncSetAttribute(local_attn, cudaFuncAttributeMaxDynamicSharedMemorySize, SMEM_ATTN);
    cudaFuncSetAttribute(gemm64x64, cudaFuncAttributeMaxDynamicSharedMemorySize, SMEM_GEMM);

    convert_split<<<4096, 256>>>(q, k, v, Wq, Wk, Wv, Wo);

    gemm64x64<<<dim3(DMODEL/64, S/64, 3), 256, SMEM_GEMM>>>(
        pxh, pxl, pwh, pqkv, nullptr);

    local_attn<<<dim3(S/64, NH), 256, SMEM_ATTN>>>(pqkv, pqkv + SD, pqkv + 2*SD, attn_w);

    gemm64x64<<<dim3(DMODEL/64, S/64, 1), 256, SMEM_GEMM>>>(
        paoh, paol, pwh + 3*DD, out, bo);
}

// round 11
// speedup vs baseline: 1.5793x; 1.0779x over previous
#include <cuda_runtime.h>
#include <cuda_fp16.h>
#include <cstdint>
#include <math.h>

#define S 2048
#define DMODEL 512
#define NH 8
#define DKH 64
#define WIN 64
#define NEGV -1000000000.0f
#define SD (S*DMODEL)
#define DD (DMODEL*DMODEL)

#define QH_STR 72     // halves per Q/K smem row
#define PA_STR 132    // fp32 words per P row (264 halves)
#define VT_STR 136    // halves per Vt row

#define LDA 40

typedef unsigned int u32;

// ---------------- device scratch (allocation-free rule) ----------------
__device__ __half g_xh[3*SD];
__device__ __half g_xl[3*SD];
__device__ __half g_Wh[4*DD];
__device__ float  g_QKV[3*SD];
__device__ __half g_AOh[SD];
__device__ __half g_AOl[SD];

// ---------------- fp32 -> fp16 split (A: hi/lo, W: hi only) ----------------
__global__ void __launch_bounds__(256) convert_split(
    const float* __restrict__ q, const float* __restrict__ k, const float* __restrict__ v,
    const float* __restrict__ Wq, const float* __restrict__ Wk,
    const float* __restrict__ Wv, const float* __restrict__ Wo)
{
    const int SD4 = SD/4;
    const int DD4 = DD/4;
    int idx = blockIdx.x * 256 + threadIdx.x;
    if (idx < 3*SD4) {
        int r = idx / SD4;
        size_t e = (size_t)(idx - r*SD4) * 4;
        const float* src = (r == 0 ? q : (r == 1 ? k : v)) + e;
        __half* dh = g_xh + (size_t)r*SD + e;
        __half* dl = g_xl + (size_t)r*SD + e;
        float4 f = *(const float4*)src;
        __half h0 = __float2half(f.x);
        __half h1 = __float2half(f.y);
        __half h2 = __float2half(f.z);
        __half h3 = __float2half(f.w);
        __half l0 = __float2half(f.x - __half2float(h0));
        __half l1 = __float2half(f.y - __half2float(h1));
        __half l2 = __float2half(f.z - __half2float(h2));
        __half l3 = __float2half(f.w - __half2float(h3));
        *(__half2*)(dh)     = __halves2half2(h0, h1);
        *(__half2*)(dh + 2) = __halves2half2(h2, h3);
        *(__half2*)(dl)     = __halves2half2(l0, l1);
        *(__half2*)(dl + 2) = __halves2half2(l2, l3);
    } else {
        int j = idx - 3*SD4;
        int r = j / DD4;
        size_t e = (size_t)(j - r*DD4) * 4;
        const float* src = (r == 0 ? Wq : (r == 1 ? Wk : (r == 2 ? Wv : Wo))) + e;
        __half* dh = g_Wh + (size_t)r*DD + e;
        float4 f = *(const float4*)src;
        *(__half2*)(dh)     = __halves2half2(__float2half(f.x), __float2half(f.y));
        *(__half2*)(dh + 2) = __halves2half2(__float2half(f.z), __float2half(f.w));
    }
}

// ---------------- tensor-core helpers ----------------
__device__ __forceinline__ void ldsm4(u32* r, u32 a) {
    asm volatile("ldmatrix.sync.aligned.m8n8.x4.shared.b16 {%0,%1,%2,%3}, [%4];"
        : "=r"(r[0]), "=r"(r[1]), "=r"(r[2]), "=r"(r[3]) : "r"(a));
}
__device__ __forceinline__ void mma_fp16(float* c, const u32* a, const u32* b) {
    asm volatile("mma.sync.aligned.m16n8k16.row.col.f32.f16.f16.f32 "
        "{%0,%1,%2,%3},{%4,%5,%6,%7},{%8,%9},{%0,%1,%2,%3};"
        : "+f"(c[0]), "+f"(c[1]), "+f"(c[2]), "+f"(c[3])
        : "r"(a[0]), "r"(a[1]), "r"(a[2]), "r"(a[3]), "r"(b[0]), "r"(b[1]));
}
__device__ __forceinline__ void cp16(u32 dst, const void* src) {
    asm volatile("cp.async.cg.shared.global [%0], [%1], 16;" :: "r"(dst), "l"(src));
}
__device__ __forceinline__ void cp_commit() {
    asm volatile("cp.async.commit_group;");
}

// ---------------- GEMM (unchanged from round 9/10) ----------------
#define STG_A (64*LDA*2)
#define STG_W (64*LDA*2)
#define SMEM_GEMM (2*(2*STG_A + STG_W))

__global__ void __launch_bounds__(256, 3) gemm64x64(
    const __half* __restrict__ Ah_, const __half* __restrict__ Al_,
    const __half* __restrict__ Wh_,
    float* __restrict__ C, const float* __restrict__ bias)
{
    extern __shared__ __align__(16) __half dsm[];

    const size_t za = (size_t)blockIdx.z * SD;
    const size_t zw = (size_t)blockIdx.z * DD;
    const int tid = threadIdx.x;
    const int m_base = blockIdx.y * 64;
    const int n_base = blockIdx.x * 64;

    const int a_row = tid >> 2;
    const int a_col = (tid & 3) * 8;

    const int lane = tid & 31;
    const int wid = tid >> 5;
    const int warp_m = wid >> 1;
    const int warp_n = wid & 1;
    const int lrow = (lane & 7) + ((lane >> 3) & 1) * 8;
    const int lcol = (lane >> 4) * 8;

    const u32 base = (u32)__cvta_generic_to_shared(dsm);
    const u32 bAh = base;
    const u32 bAl = base + 2*STG_A;
    const u32 bWh = base + 4*STG_A;

    const __half* gA = Ah_ + za + (size_t)(m_base + a_row) * DMODEL + a_col;
    const __half* gL = Al_ + za + (size_t)(m_base + a_row) * DMODEL + a_col;
    const __half* gW = Wh_ + zw + (size_t)(n_base + a_row) * DMODEL + a_col;
    float* Cz = C + za;

    const u32 aoff = (u32)((a_row * LDA + a_col) * 2);

    float acc[4][4];
    #pragma unroll
    for (int ni = 0; ni < 4; ni++) {
        #pragma unroll
        for (int t = 0; t < 4; t++) {
            acc[ni][t] = 0.0f;
        }
    }

    {
        cp16(bAh + aoff, gA);
        cp16(bAl + aoff, gL);
        cp16(bWh + aoff, gW);
        cp_commit();
    }

    for (int s = 0; s < 16; s++) {
        const u32 bufA = (u32)(s & 1) * STG_A;
        const u32 bufW = (u32)(s & 1) * STG_W;

        if (s < 15) {
            int k0 = (s + 1) * 32;
            u32 nbA = (u32)((s + 1) & 1) * STG_A;
            u32 nbW = (u32)((s + 1) & 1) * STG_W;
            cp16(bAh + nbA + aoff, gA + k0);
            cp16(bAl + nbA + aoff, gL + k0);
            cp16(bWh + nbW + aoff, gW + k0);
            cp_commit();
            asm volatile("cp.async.wait_group 1;");
        } else {
            asm volatile("cp.async.wait_group 0;");
        }
        __syncthreads();

        #pragma unroll
        for (int kb = 0; kb < 32; kb += 16) {
            u32 ah[4];
            u32 al[4];
            u32 bh[4][2];
            {
                u32 off = bufA + (u32)(((warp_m * 16 + lrow) * LDA + kb + lcol) * 2);
                ldsm4(ah, bAh + off);
                ldsm4(al, bAl + off);
            }
            #pragma unroll
            for (int g2 = 0; g2 < 2; g2++) {
                u32 off = bufW + (u32)(((warp_n * 32 + g2 * 16 + lrow) * LDA + kb + lcol) * 2);
                u32 r0[4];
                ldsm4(r0, bWh + off);
                bh[g2*2][0]   = r0[0];
                bh[g2*2+1][0] = r0[1];
                bh[g2*2][1]   = r0[2];
                bh[g2*2+1][1] = r0[3];
            }
            #pragma unroll
            for (int ni = 0; ni < 4; ni++) {
                mma_fp16(acc[ni], ah, bh[ni]);
                mma_fp16(acc[ni], al, bh[ni]);
            }
        }
        __syncthreads();
    }

    const int qr = lane >> 2;
    const int qc = (lane & 3) * 2;
    {
        int m0 = m_base + warp_m * 16 + qr;
        #pragma unroll
        for (int ni = 0; ni < 4; ni++) {
            int n = n_base + warp_n * 32 + ni * 8 + qc;
            float b0 = 0.0f;
            float b1 = 0.0f;
            if (bias) {
                b0 = bias[n];
                b1 = bias[n + 1];
            }
            float2 v0 = make_float2(acc[ni][0] + b0, acc[ni][1] + b1);
            float2 v1 = make_float2(acc[ni][2] + b0, acc[ni][3] + b1);
            *(float2*)(Cz + (size_t)m0 * DMODEL + n) = v0;
            *(float2*)(Cz + (size_t)(m0 + 8) * DMODEL + n) = v1;
        }
    }
}

// ---------------- windowed attention (scores + PV via fp16 MMA) ----------------
// smem (bytes):
//   phase1 (aliased region 0..36864):
//     Qh [64][72]h @0, Ql @9216, Ks [128][72]h @18432
//   phase2 (same region): P rows [64][132]f (fp32 scores -> fp16 hi/lo probs in place)
//   Vt [64][136]h @36864  (V transposed: Vt[dk][kk])
//   bias [65]f @54272
#define SMEM_ATTN 54592

__global__ void __launch_bounds__(256, 2) local_attn(
    const float* __restrict__ Q, const float* __restrict__ K,
    const float* __restrict__ V, float* __restrict__ attn_w)
{
    extern __shared__ __align__(16) char smc[];
    __half* Qh = (__half*)(smc);
    __half* Ql = (__half*)(smc + 9216);
    __half* Ks = (__half*)(smc + 18432);
    float*  Pf = (float*)(smc);
    __half* Phalf = (__half*)(smc);
    __half* Vt = (__half*)(smc + 36864);
    float*  bias_s = (float*)(smc + 54272);

    const int h  = blockIdx.y;
    const int i0 = blockIdx.x * 64;
    const int tid = threadIdx.x;

    if (tid <= WIN) {
        bias_s[tid] = 0.1f * expf(-0.1f * (float)(WIN - tid));
    }

    // Q tile fp16 hi/lo [qi][d]
    for (int idx = tid; idx < 64 * 64; idx += 256) {
        int qi = idx >> 6;
        int d  = idx & 63;
        float qv = Q[(size_t)(i0 + qi) * DMODEL + h * DKH + d];
        __half hh = __float2half(qv);
        Qh[qi * QH_STR + d] = hh;
        Ql[qi * QH_STR + d] = __float2half(qv - __half2float(hh));
    }
    // K fp16 [kk][d]; V fp16 transposed [d][kk]
    for (int idx = tid; idx < 128 * 64; idx += 256) {
        int kk = idx >> 6;
        int d  = idx & 63;
        int j = i0 - 64 + kk;
        int jc = (j < 0) ? 0 : j;
        Ks[kk * QH_STR + d] = __float2half(K[(size_t)jc * DMODEL + h * DKH + d]);
        Vt[d * VT_STR + kk] = __float2half(V[(size_t)jc * DMODEL + h * DKH + d]);
    }
    __syncthreads();

    const int lane = tid & 31;
    const int wid  = tid >> 5;
    const int warp_m = wid >> 1;   // 16 q-rows each
    const int warp_n = wid & 1;    // scores: 64 kk-cols each; PV: 32 dk-cols each
    const int lrow = (lane & 7) + ((lane >> 3) & 1) * 8;
    const int lcol = (lane >> 4) * 8;

    const u32 bQh = (u32)__cvta_generic_to_shared(Qh);
    const u32 bQl = (u32)__cvta_generic_to_shared(Ql);
    const u32 bKs = (u32)__cvta_generic_to_shared(Ks);
    const u32 bPf = (u32)__cvta_generic_to_shared(Pf);
    const u32 bVt = (u32)__cvta_generic_to_shared(Vt);

    // ----- score MMA: S = Q K^T -----
    float sc[8][4];
    #pragma unroll
    for (int nt = 0; nt < 8; nt++) {
        #pragma unroll
        for (int t = 0; t < 4; t++) {
            sc[nt][t] = 0.0f;
        }
    }
    #pragma unroll
    for (int kc = 0; kc < 64; kc += 16) {
        u32 ah[4];
        u32 al[4];
        u32 bf[8][2];
        {
            u32 off = (u32)(((warp_m * 16 + lrow) * QH_STR + kc + lcol) * 2);
            ldsm4(ah, bQh + off);
            ldsm4(al, bQl + off);
        }
        #pragma unroll
        for (int g = 0; g < 4; g++) {
            u32 off = (u32)(((warp_n * 64 + g * 16 + lrow) * QH_STR + kc + lcol) * 2);
            u32 r0[4];
            ldsm4(r0, bKs + off);
            bf[g*2][0]   = r0[0];
            bf[g*2+1][0] = r0[1];
            bf[g*2][1]   = r0[2];
            bf[g*2+1][1] = r0[3];
        }
        #pragma unroll
        for (int nt = 0; nt < 8; nt++) {
            mma_fp16(sc[nt], ah, bf[nt]);
            mma_fp16(sc[nt], al, bf[nt]);
        }
    }
    __syncthreads();   // all Q/K ldsm done -> region reusable as P

    // ----- mask + decay bias -> Pf[qi][kk] (row-major fp32) -----
    {
        const int qr = lane >> 2;
        const int qc = (lane & 3) * 2;
        #pragma unroll
        for (int nt = 0; nt < 8; nt++) {
            #pragma unroll
            for (int t = 0; t < 4; t++) {
                int kk = warp_n * 64 + nt * 8 + qc + (t & 1);
                int qi = warp_m * 16 + qr + (t >> 1) * 8;
                int r  = kk - qi;
                int jg = i0 - 64 + kk;
                float val = NEGV;
                if (r >= 0 && r <= WIN && jg >= 0) {
                    val = sc[nt][t] * 0.125f + bias_s[r];
                }
                Pf[qi * PA_STR + kk] = val;
            }
        }
    }
    __syncthreads();

    // ----- softmax per row; write probs back in place as fp16 hi/lo -----
    {
        for (int rr = 0; rr < 8; rr++) {
            int qi = wid * 8 + rr;
            float4 v4 = *(const float4*)&Pf[qi * PA_STR + lane * 4];
            float v[4] = {v4.x, v4.y, v4.z, v4.w};
            float mx = fmaxf(fmaxf(v[0], v[1]), fmaxf(v[2], v[3]));
            #pragma unroll
            for (int o = 16; o > 0; o >>= 1) {
                mx = fmaxf(mx, __shfl_xor_sync(0xffffffffu, mx, o));
            }
            float sum = 0.0f;
            #pragma unroll
            for (int t = 0; t < 4; t++) {
                v[t] = expf(v[t] - mx);
                sum += v[t];
            }
            #pragma unroll
            for (int o = 16; o > 0; o >>= 1) {
                sum += __shfl_xor_sync(0xffffffffu, sum, o);
            }
            float inv = 1.0f / sum;
            __half hh[4];
            __half ll[4];
            #pragma unroll
            for (int t = 0; t < 4; t++) {
                float p = v[t] * inv;
                hh[t] = __float2half(p);
                ll[t] = __float2half(p - __half2float(hh[t]));
            }
            __half* rowh = Phalf + qi * (PA_STR * 2);
            *(__half2*)(rowh + lane * 4)       = __halves2half2(hh[0], hh[1]);
            *(__half2*)(rowh + lane * 4 + 2)   = __halves2half2(hh[2], hh[3]);
            *(__half2*)(rowh + 128 + lane * 4)     = __halves2half2(ll[0], ll[1]);
            *(__half2*)(rowh + 128 + lane * 4 + 2) = __halves2half2(ll[2], ll[3]);
        }
    }
    __syncthreads();

    // ----- attn_w gather (hi+lo for full precision) -----
    for (int idx = tid; idx < 64 * 128; idx += 256) {
        int qi = idx >> 7;
        int slot = idx & 127;
        int i = i0 + qi;
        float val = 0.0f;
        const __half* rowh = Phalf + qi * (PA_STR * 2);
        if (i < WIN) {
            if (slot <= qi) {
                int kk = slot + 64;
                val = __half2float(rowh[kk]) + __half2float(rowh[128 + kk]);
            }
        } else if (i >= S - WIN) {
            if (slot <= WIN) {
                int kk = qi + slot;
                val = __half2float(rowh[kk]) + __half2float(rowh[128 + kk]);
            }
        }
        attn_w[((size_t)h * S + i) * 128 + slot] = val;
    }

    // ----- PV MMA: out = P @ V  (A = P hi/lo rows, B = Vt col-major) -----
    float acc[4][4];
    #pragma unroll
    for (int ni = 0; ni < 4; ni++) {
        #pragma unroll
        for (int t = 0; t < 4; t++) {
            acc[ni][t] = 0.0f;
        }
    }
    #pragma unroll
    for (int kc = 0; kc < 128; kc += 16) {
        u32 ah[4];
        u32 al[4];
        u32 bf[4][2];
        {
            u32 off = bPf + (u32)(((warp_m * 16 + lrow) * (PA_STR * 2) + kc + lcol) * 2);
            ldsm4(ah, off);
            ldsm4(al, off + 256);
        }
        #pragma unroll
        for (int g = 0; g < 2; g++) {
            u32 off = bVt + (u32)(((warp_n * 32 + g * 16 + lrow) * VT_STR + kc + lcol) * 2);
            u32 r0[4];
            ldsm4(r0, off);
            bf[g*2][0]   = r0[0];
            bf[g*2+1][0] = r0[1];
            bf[g*2][1]   = r0[2];
            bf[g*2+1][1] = r0[3];
        }
        #pragma unroll
        for (int ni = 0; ni < 4; ni++) {
            mma_fp16(acc[ni], ah, bf[ni]);
            mma_fp16(acc[ni], al, bf[ni]);
        }
    }

    // ----- epilogue: fragments -> g_AOh/g_AOl (fp16 hi/lo) -----
    {
        const int qr = lane >> 2;
        const int qc = (lane & 3) * 2;
        #pragma unroll
        for (int ni = 0; ni < 4; ni++) {
            int dk = warp_n * 32 + ni * 8 + qc;
            #pragma unroll
            for (int half_m = 0; half_m < 2; half_m++) {
                int qi = warp_m * 16 + qr + half_m * 8;
                size_t base = (size_t)(i0 + qi) * DMODEL + h * DKH + dk;
                float v0 = acc[ni][half_m * 2];
                float v1 = acc[ni][half_m * 2 + 1];
                __half h0 = __float2half(v0);
                __half h1 = __float2half(v1);
                __half l0 = __float2half(v0 - __half2float(h0));
                __half l1 = __float2half(v1 - __half2float(h1));
                *(__half2*)(g_AOh + base) = __halves2half2(h0, h1);
                *(__half2*)(g_AOl + base) = __halves2half2(l0, l1);
            }
        }
    }
}

// ---------------- launch ----------------
extern "C" void kernel_launch(void* const* d_in, const int* in_sizes, int n_in,
                              void* d_out, int out_size) {
    const float* q  = (const float*)d_in[0];
    const float* k  = (const float*)d_in[1];
    const float* v  = (const float*)d_in[2];
    const float* Wq = (const float*)d_in[3];
    const float* Wk = (const float*)d_in[4];
    const float* Wv = (const float*)d_in[5];
    const float* Wo = (const float*)d_in[6];
    const float* bo = (const float*)d_in[7];

    float* out    = (float*)d_out;
    float* attn_w = out + (size_t)SD;

    __half* pxh;
    __half* pxl;
    __half* pwh;
    __half* paoh;
    __half* paol;
    float* pqkv;
    cudaGetSymbolAddress((void**)&pxh,  g_xh);
    cudaGetSymbolAddress((void**)&pxl,  g_xl);
    cudaGetSymbolAddress((void**)&pwh,  g_Wh);
    cudaGetSymbolAddress((void**)&pqkv, g_QKV);
    cudaGetSymbolAddress((void**)&paoh, g_AOh);
    cudaGetSymbolAddress((void**)&paol, g_AOl);

    cudaFuncSetAttribute(local_attn, cudaFuncAttributeMaxDynamicSharedMemorySize, SMEM_ATTN);
    cudaFuncSetAttribute(gemm64x64, cudaFuncAttributeMaxDynamicSharedMemorySize, SMEM_GEMM);

    convert_split<<<4096, 256>>>(q, k, v, Wq, Wk, Wv, Wo);

    gemm64x64<<<dim3(DMODEL/64, S/64, 3), 256, SMEM_GEMM>>>(
        pxh, pxl, pwh, pqkv, nullptr);

    local_attn<<<dim3(S/64, NH), 256, SMEM_ATTN>>>(pqkv, pqkv + SD, pqkv + 2*SD, attn_w);

    gemm64x64<<<dim3(DMODEL/64, S/64, 1), 256, SMEM_GEMM>>>(
        paoh, paol, pwh + 3*DD, out, bo);
}

// round 12
// speedup vs baseline: 1.9472x; 1.2330x over previous
#include <cuda_runtime.h>
#include <cuda_fp16.h>
#include <cstdint>
#include <math.h>

#define S 2048
#define DMODEL 512
#define NH 8
#define DKH 64
#define WIN 64
#define NEGV -1000000000.0f
#define SD (S*DMODEL)
#define DD (DMODEL*DMODEL)

#define QH_STR 72     // halves per Q/K smem row
#define PA_STR 132    // fp32 words per P row (264 halves)
#define VT_STR 136    // halves per Vt row

#define LDA 40

typedef unsigned int u32;

// ---------------- device scratch (allocation-free rule) ----------------
__device__ __half g_xh[3*SD];     // activations fp16
__device__ __half g_Wh[4*DD];     // weights fp16
__device__ float  g_QKV[3*SD];
__device__ __half g_AOh[SD];      // attention output fp16

// ---------------- fp32 -> fp16 convert ----------------
__global__ void __launch_bounds__(256) convert_fp16(
    const float* __restrict__ q, const float* __restrict__ k, const float* __restrict__ v,
    const float* __restrict__ Wq, const float* __restrict__ Wk,
    const float* __restrict__ Wv, const float* __restrict__ Wo)
{
    const int SD4 = SD/4;
    const int DD4 = DD/4;
    int idx = blockIdx.x * 256 + threadIdx.x;
    const float* src;
    __half* dh;
    if (idx < 3*SD4) {
        int r = idx / SD4;
        size_t e = (size_t)(idx - r*SD4) * 4;
        src = (r == 0 ? q : (r == 1 ? k : v)) + e;
        dh = g_xh + (size_t)r*SD + e;
    } else {
        int j = idx - 3*SD4;
        int r = j / DD4;
        size_t e = (size_t)(j - r*DD4) * 4;
        src = (r == 0 ? Wq : (r == 1 ? Wk : (r == 2 ? Wv : Wo))) + e;
        dh = g_Wh + (size_t)r*DD + e;
    }
    float4 f = *(const float4*)src;
    *(__half2*)(dh)     = __halves2half2(__float2half(f.x), __float2half(f.y));
    *(__half2*)(dh + 2) = __halves2half2(__float2half(f.z), __float2half(f.w));
}

// ---------------- tensor-core helpers ----------------
__device__ __forceinline__ void ldsm4(u32* r, u32 a) {
    asm volatile("ldmatrix.sync.aligned.m8n8.x4.shared.b16 {%0,%1,%2,%3}, [%4];"
        : "=r"(r[0]), "=r"(r[1]), "=r"(r[2]), "=r"(r[3]) : "r"(a));
}
__device__ __forceinline__ void mma_fp16(float* c, const u32* a, const u32* b) {
    asm volatile("mma.sync.aligned.m16n8k16.row.col.f32.f16.f16.f32 "
        "{%0,%1,%2,%3},{%4,%5,%6,%7},{%8,%9},{%0,%1,%2,%3};"
        : "+f"(c[0]), "+f"(c[1]), "+f"(c[2]), "+f"(c[3])
        : "r"(a[0]), "r"(a[1]), "r"(a[2]), "r"(a[3]), "r"(b[0]), "r"(b[1]));
}
__device__ __forceinline__ void cp16(u32 dst, const void* src) {
    asm volatile("cp.async.cg.shared.global [%0], [%1], 16;" :: "r"(dst), "l"(src));
}
__device__ __forceinline__ void cp_commit() {
    asm volatile("cp.async.commit_group;");
}

// ---------------- GEMM: C = A @ W^T (+bias), plain fp16, 64x64 tile ----------------
#define STG_T (64*LDA*2)
#define SMEM_GEMM (2*2*STG_T)

__global__ void __launch_bounds__(256, 3) gemm64x64(
    const __half* __restrict__ A_, const __half* __restrict__ W_,
    float* __restrict__ C, const float* __restrict__ bias)
{
    extern __shared__ __align__(16) __half dsm[];

    const size_t za = (size_t)blockIdx.z * SD;
    const size_t zw = (size_t)blockIdx.z * DD;
    const int tid = threadIdx.x;
    const int m_base = blockIdx.y * 64;
    const int n_base = blockIdx.x * 64;

    const int a_row = tid >> 2;
    const int a_col = (tid & 3) * 8;

    const int lane = tid & 31;
    const int wid = tid >> 5;
    const int warp_m = wid >> 1;
    const int warp_n = wid & 1;
    const int lrow = (lane & 7) + ((lane >> 3) & 1) * 8;
    const int lcol = (lane >> 4) * 8;

    const u32 base = (u32)__cvta_generic_to_shared(dsm);
    const u32 bA = base;
    const u32 bW = base + 2*STG_T;

    const __half* gA = A_ + za + (size_t)(m_base + a_row) * DMODEL + a_col;
    const __half* gW = W_ + zw + (size_t)(n_base + a_row) * DMODEL + a_col;
    float* Cz = C + za;

    const u32 aoff = (u32)((a_row * LDA + a_col) * 2);

    float acc[4][4];
    #pragma unroll
    for (int ni = 0; ni < 4; ni++) {
        #pragma unroll
        for (int t = 0; t < 4; t++) {
            acc[ni][t] = 0.0f;
        }
    }

    {
        cp16(bA + aoff, gA);
        cp16(bW + aoff, gW);
        cp_commit();
    }

    for (int s = 0; s < 16; s++) {
        const u32 buf = (u32)(s & 1) * STG_T;

        if (s < 15) {
            int k0 = (s + 1) * 32;
            u32 nb = (u32)((s + 1) & 1) * STG_T;
            cp16(bA + nb + aoff, gA + k0);
            cp16(bW + nb + aoff, gW + k0);
            cp_commit();
            asm volatile("cp.async.wait_group 1;");
        } else {
            asm volatile("cp.async.wait_group 0;");
        }
        __syncthreads();

        #pragma unroll
        for (int kb = 0; kb < 32; kb += 16) {
            u32 ah[4];
            u32 bh[4][2];
            {
                u32 off = buf + (u32)(((warp_m * 16 + lrow) * LDA + kb + lcol) * 2);
                ldsm4(ah, bA + off);
            }
            #pragma unroll
            for (int g2 = 0; g2 < 2; g2++) {
                u32 off = buf + (u32)(((warp_n * 32 + g2 * 16 + lrow) * LDA + kb + lcol) * 2);
                u32 r0[4];
                ldsm4(r0, bW + off);
                bh[g2*2][0]   = r0[0];
                bh[g2*2+1][0] = r0[1];
                bh[g2*2][1]   = r0[2];
                bh[g2*2+1][1] = r0[3];
            }
            #pragma unroll
            for (int ni = 0; ni < 4; ni++) {
                mma_fp16(acc[ni], ah, bh[ni]);
            }
        }
        __syncthreads();
    }

    const int qr = lane >> 2;
    const int qc = (lane & 3) * 2;
    {
        int m0 = m_base + warp_m * 16 + qr;
        #pragma unroll
        for (int ni = 0; ni < 4; ni++) {
            int n = n_base + warp_n * 32 + ni * 8 + qc;
            float b0 = 0.0f;
            float b1 = 0.0f;
            if (bias) {
                b0 = bias[n];
                b1 = bias[n + 1];
            }
            float2 v0 = make_float2(acc[ni][0] + b0, acc[ni][1] + b1);
            float2 v1 = make_float2(acc[ni][2] + b0, acc[ni][3] + b1);
            *(float2*)(Cz + (size_t)m0 * DMODEL + n) = v0;
            *(float2*)(Cz + (size_t)(m0 + 8) * DMODEL + n) = v1;
        }
    }
}

// ---------------- windowed attention (scores + PV via fp16 MMA) ----------------
// smem (bytes):
//   phase1 (aliased 0..27648): Qh [64][72]h @0, Ks [128][72]h @9216
//   phase2 (same region, extends to 33792): P rows [64][132]f -> fp16 hi/lo probs
//   Vt [64][136]h @33792
//   bias [65]f @51200
#define SMEM_ATTN 51520

__global__ void __launch_bounds__(256, 2) local_attn(
    const float* __restrict__ Q, const float* __restrict__ K,
    const float* __restrict__ V, float* __restrict__ attn_w)
{
    extern __shared__ __align__(16) char smc[];
    __half* Qh = (__half*)(smc);
    __half* Ks = (__half*)(smc + 9216);
    float*  Pf = (float*)(smc);
    __half* Phalf = (__half*)(smc);
    __half* Vt = (__half*)(smc + 33792);
    float*  bias_s = (float*)(smc + 51200);

    const int h  = blockIdx.y;
    const int i0 = blockIdx.x * 64;
    const int tid = threadIdx.x;

    if (tid <= WIN) {
        bias_s[tid] = 0.1f * expf(-0.1f * (float)(WIN - tid));
    }

    // Q tile fp16 [qi][d]
    for (int idx = tid; idx < 64 * 64; idx += 256) {
        int qi = idx >> 6;
        int d  = idx & 63;
        Qh[qi * QH_STR + d] = __float2half(Q[(size_t)(i0 + qi) * DMODEL + h * DKH + d]);
    }
    // K fp16 [kk][d]; V fp16 transposed [d][kk]
    for (int idx = tid; idx < 128 * 64; idx += 256) {
        int kk = idx >> 6;
        int d  = idx & 63;
        int j = i0 - 64 + kk;
        int jc = (j < 0) ? 0 : j;
        Ks[kk * QH_STR + d] = __float2half(K[(size_t)jc * DMODEL + h * DKH + d]);
        Vt[d * VT_STR + kk] = __float2half(V[(size_t)jc * DMODEL + h * DKH + d]);
    }
    __syncthreads();

    const int lane = tid & 31;
    const int wid  = tid >> 5;
    const int warp_m = wid >> 1;   // 16 q-rows each
    const int warp_n = wid & 1;    // scores: 64 kk-cols; PV: 32 dk-cols
    const int lrow = (lane & 7) + ((lane >> 3) & 1) * 8;
    const int lcol = (lane >> 4) * 8;

    const u32 bQh = (u32)__cvta_generic_to_shared(Qh);
    const u32 bKs = (u32)__cvta_generic_to_shared(Ks);
    const u32 bPf = (u32)__cvta_generic_to_shared(Pf);
    const u32 bVt = (u32)__cvta_generic_to_shared(Vt);

    // ----- score MMA: S = Q K^T -----
    float sc[8][4];
    #pragma unroll
    for (int nt = 0; nt < 8; nt++) {
        #pragma unroll
        for (int t = 0; t < 4; t++) {
            sc[nt][t] = 0.0f;
        }
    }
    #pragma unroll
    for (int kc = 0; kc < 64; kc += 16) {
        u32 ah[4];
        u32 bf[8][2];
        {
            u32 off = (u32)(((warp_m * 16 + lrow) * QH_STR + kc + lcol) * 2);
            ldsm4(ah, bQh + off);
        }
        #pragma unroll
        for (int g = 0; g < 4; g++) {
            u32 off = (u32)(((warp_n * 64 + g * 16 + lrow) * QH_STR + kc + lcol) * 2);
            u32 r0[4];
            ldsm4(r0, bKs + off);
            bf[g*2][0]   = r0[0];
            bf[g*2+1][0] = r0[1];
            bf[g*2][1]   = r0[2];
            bf[g*2+1][1] = r0[3];
        }
        #pragma unroll
        for (int nt = 0; nt < 8; nt++) {
            mma_fp16(sc[nt], ah, bf[nt]);
        }
    }
    __syncthreads();   // Q/K reads done -> region reusable as P

    // ----- mask + decay bias -> Pf[qi][kk] -----
    {
        const int qr = lane >> 2;
        const int qc = (lane & 3) * 2;
        #pragma unroll
        for (int nt = 0; nt < 8; nt++) {
            #pragma unroll
            for (int t = 0; t < 4; t++) {
                int kk = warp_n * 64 + nt * 8 + qc + (t & 1);
                int qi = warp_m * 16 + qr + (t >> 1) * 8;
                int r  = kk - qi;
                int jg = i0 - 64 + kk;
                float val = NEGV;
                if (r >= 0 && r <= WIN && jg >= 0) {
                    val = sc[nt][t] * 0.125f + bias_s[r];
                }
                Pf[qi * PA_STR + kk] = val;
            }
        }
    }
    __syncthreads();

    // ----- softmax per row; probs in place as fp16 hi/lo -----
    {
        for (int rr = 0; rr < 8; rr++) {
            int qi = wid * 8 + rr;
            float4 v4 = *(const float4*)&Pf[qi * PA_STR + lane * 4];
            float v[4] = {v4.x, v4.y, v4.z, v4.w};
            float mx = fmaxf(fmaxf(v[0], v[1]), fmaxf(v[2], v[3]));
            #pragma unroll
            for (int o = 16; o > 0; o >>= 1) {
                mx = fmaxf(mx, __shfl_xor_sync(0xffffffffu, mx, o));
            }
            float sum = 0.0f;
            #pragma unroll
            for (int t = 0; t < 4; t++) {
                v[t] = expf(v[t] - mx);
                sum += v[t];
            }
            #pragma unroll
            for (int o = 16; o > 0; o >>= 1) {
                sum += __shfl_xor_sync(0xffffffffu, sum, o);
            }
            float inv = 1.0f / sum;
            __half hh[4];
            __half ll[4];
            #pragma unroll
            for (int t = 0; t < 4; t++) {
                float p = v[t] * inv;
                hh[t] = __float2half(p);
                ll[t] = __float2half(p - __half2float(hh[t]));
            }
            __half* rowh = Phalf + qi * (PA_STR * 2);
            *(__half2*)(rowh + lane * 4)       = __halves2half2(hh[0], hh[1]);
            *(__half2*)(rowh + lane * 4 + 2)   = __halves2half2(hh[2], hh[3]);
            *(__half2*)(rowh + 128 + lane * 4)     = __halves2half2(ll[0], ll[1]);
            *(__half2*)(rowh + 128 + lane * 4 + 2) = __halves2half2(ll[2], ll[3]);
        }
    }
    __syncthreads();

    // ----- attn_w gather (hi+lo, full precision) -----
    for (int idx = tid; idx < 64 * 128; idx += 256) {
        int qi = idx >> 7;
        int slot = idx & 127;
        int i = i0 + qi;
        float val = 0.0f;
        const __half* rowh = Phalf + qi * (PA_STR * 2);
        if (i < WIN) {
            if (slot <= qi) {
                int kk = slot + 64;
                val = __half2float(rowh[kk]) + __half2float(rowh[128 + kk]);
            }
        } else if (i >= S - WIN) {
            if (slot <= WIN) {
                int kk = qi + slot;
                val = __half2float(rowh[kk]) + __half2float(rowh[128 + kk]);
            }
        }
        attn_w[((size_t)h * S + i) * 128 + slot] = val;
    }

    // ----- PV MMA (P hi only): out = P @ V -----
    float acc[4][4];
    #pragma unroll
    for (int ni = 0; ni < 4; ni++) {
        #pragma unroll
        for (int t = 0; t < 4; t++) {
            acc[ni][t] = 0.0f;
        }
    }
    #pragma unroll
    for (int kc = 0; kc < 128; kc += 16) {
        u32 ah[4];
        u32 bf[4][2];
        {
            u32 off = bPf + (u32)(((warp_m * 16 + lrow) * (PA_STR * 2) + kc + lcol) * 2);
            ldsm4(ah, off);
        }
        #pragma unroll
        for (int g = 0; g < 2; g++) {
            u32 off = bVt + (u32)(((warp_n * 32 + g * 16 + lrow) * VT_STR + kc + lcol) * 2);
            u32 r0[4];
            ldsm4(r0, off);
            bf[g*2][0]   = r0[0];
            bf[g*2+1][0] = r0[1];
            bf[g*2][1]   = r0[2];
            bf[g*2+1][1] = r0[3];
        }
        #pragma unroll
        for (int ni = 0; ni < 4; ni++) {
            mma_fp16(acc[ni], ah, bf[ni]);
        }
    }

    // ----- epilogue: fragments -> g_AOh (fp16) -----
    {
        const int qr = lane >> 2;
        const int qc = (lane & 3) * 2;
        #pragma unroll
        for (int ni = 0; ni < 4; ni++) {
            int dk = warp_n * 32 + ni * 8 + qc;
            #pragma unroll
            for (int half_m = 0; half_m < 2; half_m++) {
                int qi = warp_m * 16 + qr + half_m * 8;
                size_t base = (size_t)(i0 + qi) * DMODEL + h * DKH + dk;
                *(__half2*)(g_AOh + base) = __halves2half2(
                    __float2half(acc[ni][half_m * 2]),
                    __float2half(acc[ni][half_m * 2 + 1]));
            }
        }
    }
}

// ---------------- launch ----------------
extern "C" void kernel_launch(void* const* d_in, const int* in_sizes, int n_in,
                              void* d_out, int out_size) {
    const float* q  = (const float*)d_in[0];
    const float* k  = (const float*)d_in[1];
    const float* v  = (const float*)d_in[2];
    const float* Wq = (const float*)d_in[3];
    const float* Wk = (const float*)d_in[4];
    const float* Wv = (const float*)d_in[5];
    const float* Wo = (const float*)d_in[6];
    const float* bo = (const float*)d_in[7];

    float* out    = (float*)d_out;
    float* attn_w = out + (size_t)SD;

    __half* pxh;
    __half* pwh;
    __half* paoh;
    float* pqkv;
    cudaGetSymbolAddress((void**)&pxh,  g_xh);
    cudaGetSymbolAddress((void**)&pwh,  g_Wh);
    cudaGetSymbolAddress((void**)&pqkv, g_QKV);
    cudaGetSymbolAddress((void**)&paoh, g_AOh);

    cudaFuncSetAttribute(local_attn, cudaFuncAttributeMaxDynamicSharedMemorySize, SMEM_ATTN);
    cudaFuncSetAttribute(gemm64x64, cudaFuncAttributeMaxDynamicSharedMemorySize, SMEM_GEMM);

    convert_fp16<<<4096, 256>>>(q, k, v, Wq, Wk, Wv, Wo);

    gemm64x64<<<dim3(DMODEL/64, S/64, 3), 256, SMEM_GEMM>>>(
        pxh, pwh, pqkv, nullptr);

    local_attn<<<dim3(S/64, NH), 256, SMEM_ATTN>>>(pqkv, pqkv + SD, pqkv + 2*SD, attn_w);

    gemm64x64<<<dim3(DMODEL/64, S/64, 1), 256, SMEM_GEMM>>>(
        paoh, pwh + 3*DD, out, bo);
}